// round 1
// baseline (speedup 1.0000x reference)
#include <cuda_runtime.h>
#include <math.h>
#include <stdint.h>

#define NB    16384
#define ND    256
#define NF    1024
#define NO    256
#define NE    8
#define NS    2
#define NES   6

// ---------------- device scratch (no allocations allowed) ----------------
__device__ int   g_cnt[NES];
__device__ int   g_tok[NES * NB];
__device__ float g_tw [NES * NB];

__global__ void zero_cnt_kernel() {
    if (threadIdx.x < NES) g_cnt[threadIdx.x] = 0;
}

// ---------------- gating: logits, softmax, weights out, top-2 routing ----
__global__ __launch_bounds__(256) void gate_kernel(
    const float* __restrict__ x,
    const float* __restrict__ gw,   // [D, E] row-major
    const float* __restrict__ gb,   // [E]
    float* __restrict__ wout)       // [B, E]
{
    __shared__ float sgw[ND * NE];
    __shared__ float sgb[NE];
    int tid = threadIdx.x;
    for (int i = tid; i < ND * NE; i += 256) sgw[i] = gw[i];
    if (tid < NE) sgb[tid] = gb[tid];
    __syncthreads();

    int warp = tid >> 5, lane = tid & 31;
    int t = blockIdx.x * 8 + warp;

    const float* xr = x + (size_t)t * ND;
    float acc[NE];
    #pragma unroll
    for (int e = 0; e < NE; e++) acc[e] = 0.f;

    #pragma unroll
    for (int r = 0; r < ND / 32; r++) {
        int d = r * 32 + lane;
        float xv = xr[d];
        const float* g = &sgw[d * NE];
        #pragma unroll
        for (int e = 0; e < NE; e++) acc[e] += xv * g[e];
    }
    #pragma unroll
    for (int e = 0; e < NE; e++) {
        float v = acc[e];
        #pragma unroll
        for (int off = 16; off > 0; off >>= 1)
            v += __shfl_xor_sync(0xFFFFFFFFu, v, off);
        acc[e] = v + sgb[e];
    }
    // softmax (all lanes compute identically)
    float m = acc[0];
    #pragma unroll
    for (int e = 1; e < NE; e++) m = fmaxf(m, acc[e]);
    float s = 0.f;
    float w[NE];
    #pragma unroll
    for (int e = 0; e < NE; e++) { w[e] = expf(acc[e] - m); s += w[e]; }
    float inv = 1.f / s;
    #pragma unroll
    for (int e = 0; e < NE; e++) w[e] *= inv;

    if (lane < NE) wout[(size_t)t * NE + lane] = w[lane];

    if (lane == 0) {
        int i1 = 0; float v1 = w[0];
        #pragma unroll
        for (int e = 1; e < NE; e++) if (w[e] > v1) { v1 = w[e]; i1 = e; }
        int i2 = -1; float v2 = -1.f;
        #pragma unroll
        for (int e = 0; e < NE; e++) if (e != i1 && w[e] > v2) { v2 = w[e]; i2 = e; }
        // push routed picks
        if (i1 >= NS) {
            int ex = i1 - NS;
            int p = atomicAdd(&g_cnt[ex], 1);
            g_tok[ex * NB + p] = t; g_tw[ex * NB + p] = v1;
        }
        if (i2 >= NS) {
            int ex = i2 - NS;
            int p = atomicAdd(&g_cnt[ex], 1);
            g_tok[ex * NB + p] = t; g_tw[ex * NB + p] = v2;
        }
    }
}

// ---------------- fused 2-layer MLP tile: 64 tokens x 256 outputs --------
struct SM {
    float xs [64][36];    // x K-chunk (32) per 64 rows, padded
    float w1s[32][68];    // W1 chunk [32K x 64F], padded
    float hs [64][68];    // relu(h) chunk [64 x 64F], padded
    float w2s[8][260];    // W2 sub-chunk [8F x 256O], padded
    int   toks[64];
    float tws [64];
};

// acc[i][j] covers row (ty*8+i) of the tile, column (tx + j*32) of output.
__device__ __forceinline__ void mlp_tile(
    SM& sm,
    const float* __restrict__ x,
    const float* __restrict__ w1,   // [D, F]
    const float* __restrict__ b1,   // [F]
    const float* __restrict__ w2,   // [F, O]
    float acc[8][8])
{
    int tid = threadIdx.x;
    int ty1 = tid >> 4, tx1 = tid & 15;   // GEMM1 grid: 16x16 threads, 4x4 micro
    int ty  = tid >> 5, tx  = tid & 31;   // GEMM2 grid: 8x32 threads, 8x8 micro

    #pragma unroll 1
    for (int fc = 0; fc < NF; fc += 64) {
        float hacc[4][4];
        #pragma unroll
        for (int i = 0; i < 4; i++)
            #pragma unroll
            for (int j = 0; j < 4; j++) hacc[i][j] = 0.f;

        // ---- GEMM1: h[64x64] = x[64x256] @ W1[256x64] ----
        #pragma unroll 1
        for (int kc = 0; kc < ND; kc += 32) {
            // load xs: 512 float4 / 256 threads
            #pragma unroll
            for (int it = 0; it < 2; it++) {
                int q = tid + it * 256;
                int row = q >> 3, f4 = q & 7;
                int gr = sm.toks[row];
                float4 v = *(const float4*)(x + (size_t)gr * ND + kc + f4 * 4);
                *(float4*)&sm.xs[row][f4 * 4] = v;
            }
            // load w1s: 512 float4 / 256 threads
            #pragma unroll
            for (int it = 0; it < 2; it++) {
                int q = tid + it * 256;
                int row = q >> 4, f4 = q & 15;
                float4 v = *(const float4*)(w1 + (size_t)(kc + row) * NF + fc + f4 * 4);
                *(float4*)&sm.w1s[row][f4 * 4] = v;
            }
            __syncthreads();
            #pragma unroll
            for (int kk = 0; kk < 32; kk++) {
                float xv[4];
                #pragma unroll
                for (int i = 0; i < 4; i++) xv[i] = sm.xs[ty1 * 4 + i][kk];
                float4 wv = *(const float4*)&sm.w1s[kk][tx1 * 4];
                float wa0 = wv.x, wa1 = wv.y, wa2 = wv.z, wa3 = wv.w;
                #pragma unroll
                for (int i = 0; i < 4; i++) {
                    hacc[i][0] += xv[i] * wa0;
                    hacc[i][1] += xv[i] * wa1;
                    hacc[i][2] += xv[i] * wa2;
                    hacc[i][3] += xv[i] * wa3;
                }
            }
            __syncthreads();
        }
        // ---- bias + relu -> hs ----
        {
            float bj[4];
            #pragma unroll
            for (int j = 0; j < 4; j++) bj[j] = b1[fc + tx1 * 4 + j];
            #pragma unroll
            for (int i = 0; i < 4; i++) {
                float4 hv;
                hv.x = fmaxf(hacc[i][0] + bj[0], 0.f);
                hv.y = fmaxf(hacc[i][1] + bj[1], 0.f);
                hv.z = fmaxf(hacc[i][2] + bj[2], 0.f);
                hv.w = fmaxf(hacc[i][3] + bj[3], 0.f);
                *(float4*)&sm.hs[ty1 * 4 + i][tx1 * 4] = hv;
            }
        }
        __syncthreads();
        // ---- GEMM2: acc[64x256] += h[64x64] @ W2[64x256] ----
        #pragma unroll 1
        for (int kc2 = 0; kc2 < 64; kc2 += 8) {
            #pragma unroll
            for (int it = 0; it < 2; it++) {
                int q = tid + it * 256;
                int row = q >> 6, f4 = q & 63;
                float4 v = *(const float4*)(w2 + (size_t)(fc + kc2 + row) * NO + f4 * 4);
                *(float4*)&sm.w2s[row][f4 * 4] = v;
            }
            __syncthreads();
            #pragma unroll
            for (int kk = 0; kk < 8; kk++) {
                float hv[8];
                #pragma unroll
                for (int i = 0; i < 8; i++) hv[i] = sm.hs[ty * 8 + i][kc2 + kk];
                float wv[8];
                #pragma unroll
                for (int j = 0; j < 8; j++) wv[j] = sm.w2s[kk][tx + j * 32];
                #pragma unroll
                for (int i = 0; i < 8; i++)
                    #pragma unroll
                    for (int j = 0; j < 8; j++)
                        acc[i][j] += hv[i] * wv[j];
            }
            __syncthreads();
        }
    }
}

// ---------------- shared experts: dense, mean of 2 ----------------------
__global__ __launch_bounds__(256) void shared_kernel(
    const float* __restrict__ x,
    const float* __restrict__ w1, const float* __restrict__ b1,
    const float* __restrict__ w2, const float* __restrict__ b2,
    float* __restrict__ out)
{
    __shared__ SM sm;
    int tid = threadIdx.x;
    int t0 = blockIdx.x * 64;
    if (tid < 64) sm.toks[tid] = t0 + tid;
    __syncthreads();

    float acc[8][8];
    #pragma unroll
    for (int i = 0; i < 8; i++)
        #pragma unroll
        for (int j = 0; j < 8; j++) acc[i][j] = 0.f;

    #pragma unroll 1
    for (int s = 0; s < NS; s++) {
        mlp_tile(sm, x,
                 w1 + (size_t)s * ND * NF, b1 + (size_t)s * NF,
                 w2 + (size_t)s * NF * NO, acc);
    }

    int ty = tid >> 5, tx = tid & 31;
    #pragma unroll
    for (int j = 0; j < 8; j++) {
        int col = tx + j * 32;
        float bb = 0.5f * (b2[col] + b2[NO + col]);
        #pragma unroll
        for (int i = 0; i < 8; i++) {
            int row = t0 + ty * 8 + i;
            out[(size_t)row * NO + col] = 0.5f * acc[i][j] + bb;
        }
    }
}

// ---------------- routed experts: sparse buckets, atomic accumulate -----
__global__ __launch_bounds__(256) void specific_kernel(
    const float* __restrict__ x,
    const float* __restrict__ w1, const float* __restrict__ b1,
    const float* __restrict__ w2, const float* __restrict__ b2,
    float* __restrict__ out)
{
    int e = blockIdx.y;
    int n = g_cnt[e];
    int base = blockIdx.x * 64;
    if (base >= n) return;

    __shared__ SM sm;
    int tid = threadIdx.x;
    if (tid < 64) {
        int p = base + tid;
        bool ok = (p < n);
        sm.toks[tid] = ok ? g_tok[e * NB + p] : 0;
        sm.tws [tid] = ok ? g_tw [e * NB + p] : 0.f;
    }
    __syncthreads();

    float acc[8][8];
    #pragma unroll
    for (int i = 0; i < 8; i++)
        #pragma unroll
        for (int j = 0; j < 8; j++) acc[i][j] = 0.f;

    mlp_tile(sm, x,
             w1 + (size_t)e * ND * NF, b1 + (size_t)e * NF,
             w2 + (size_t)e * NF * NO, acc);

    int ty = tid >> 5, tx = tid & 31;
    #pragma unroll
    for (int i = 0; i < 8; i++) {
        int r = ty * 8 + i;
        if (base + r >= n) continue;
        int t = sm.toks[r];
        float wt = sm.tws[r];
        #pragma unroll
        for (int j = 0; j < 8; j++) {
            int col = tx + j * 32;
            atomicAdd(&out[(size_t)t * NO + col], wt * (acc[i][j] + b2[e * NO + col]));
        }
    }
}

// ---------------- launch --------------------------------------------------
extern "C" void kernel_launch(void* const* d_in, const int* in_sizes, int n_in,
                              void* d_out, int out_size)
{
    const float* x      = (const float*)d_in[0];
    const float* gate_w = (const float*)d_in[1];
    const float* gate_b = (const float*)d_in[2];
    const float* sh_w1  = (const float*)d_in[3];
    const float* sh_b1  = (const float*)d_in[4];
    const float* sh_w2  = (const float*)d_in[5];
    const float* sh_b2  = (const float*)d_in[6];
    const float* sp_w1  = (const float*)d_in[7];
    const float* sp_b1  = (const float*)d_in[8];
    const float* sp_w2  = (const float*)d_in[9];
    const float* sp_b2  = (const float*)d_in[10];

    float* out  = (float*)d_out;                 // [B, O]
    float* wout = out + (size_t)NB * NO;         // [B, E]

    zero_cnt_kernel<<<1, 32>>>();
    gate_kernel<<<NB / 8, 256>>>(x, gate_w, gate_b, wout);
    shared_kernel<<<NB / 64, 256>>>(x, sh_w1, sh_b1, sh_w2, sh_b2, out);
    specific_kernel<<<dim3(NB / 64, NES), 256>>>(x, sp_w1, sp_b1, sp_w2, sp_b2, out);
}

// round 5
// speedup vs baseline: 1.7351x; 1.7351x over previous
#include <cuda_runtime.h>
#include <cuda_bf16.h>
#include <math.h>
#include <stdint.h>

#define NB 16384
#define ND 256
#define NF 1024
#define NO 256
#define NE 8
#define NS 2
#define NES 6
#define MT 64

// smem row strides in bytes (pad 16B to avoid ldmatrix bank conflicts)
#define XSB 528    // 256 bf16 + 8 pad
#define HSB 144    // 64 bf16 + 8 pad
#define W1SB 144
#define W2SB 528

// dynamic smem layout (bytes)
#define OFF_TOK 0
#define OFF_WT  256
#define OFF_B1  512
#define OFF_XH  768
#define OFF_XL  (OFF_XH + MT * XSB)
#define OFF_HH  (OFF_XL + MT * XSB)
#define OFF_HL  (OFF_HH + MT * HSB)
#define OFF_W1H (OFF_HL + MT * HSB)
#define OFF_W1L (OFF_W1H + 64 * W1SB)
#define OFF_W2H (OFF_W1L + 64 * W1SB)
#define OFF_W2L (OFF_W2H + 32 * W2SB)
#define DSM_BYTES (OFF_W2L + 32 * W2SB)   // ~139 KB

// ---------------- device scratch (small, like passing R1) ------------------
__device__ int   g_cnt[NES];
__device__ int   g_tok[NES * NB];
__device__ float g_tw [NES * NB];

// ---------------- PTX helpers ----------------------------------------------
__device__ __forceinline__ void ldsm_x4(uint32_t* a, uint32_t addr) {
    asm volatile("ldmatrix.sync.aligned.m8n8.x4.shared.b16 {%0,%1,%2,%3}, [%4];"
                 : "=r"(a[0]), "=r"(a[1]), "=r"(a[2]), "=r"(a[3]) : "r"(addr));
}
__device__ __forceinline__ void ldsm_x2t(uint32_t& b0, uint32_t& b1, uint32_t addr) {
    asm volatile("ldmatrix.sync.aligned.m8n8.x2.trans.shared.b16 {%0,%1}, [%2];"
                 : "=r"(b0), "=r"(b1) : "r"(addr));
}
__device__ __forceinline__ void mma16816(float* c, const uint32_t* a,
                                         uint32_t b0, uint32_t b1) {
    asm volatile(
        "mma.sync.aligned.m16n8k16.row.col.f32.bf16.bf16.f32 "
        "{%0,%1,%2,%3}, {%4,%5,%6,%7}, {%8,%9}, {%0,%1,%2,%3};"
        : "+f"(c[0]), "+f"(c[1]), "+f"(c[2]), "+f"(c[3])
        : "r"(a[0]), "r"(a[1]), "r"(a[2]), "r"(a[3]), "r"(b0), "r"(b1));
}
// split two fp32 into packed bf16x2 (hi) and bf16x2 (lo residual)
__device__ __forceinline__ void split2(float a, float b, uint32_t& hi, uint32_t& lo) {
    __nv_bfloat16 ha = __float2bfloat16_rn(a);
    __nv_bfloat16 hb = __float2bfloat16_rn(b);
    __nv_bfloat16 la = __float2bfloat16_rn(a - __bfloat162float(ha));
    __nv_bfloat16 lb = __float2bfloat16_rn(b - __bfloat162float(hb));
    hi = (uint32_t)__bfloat16_as_ushort(ha) | ((uint32_t)__bfloat16_as_ushort(hb) << 16);
    lo = (uint32_t)__bfloat16_as_ushort(la) | ((uint32_t)__bfloat16_as_ushort(lb) << 16);
}
// float4 -> uint2(hi bf16 x4) + uint2(lo bf16 x4)
__device__ __forceinline__ void split4(float4 v, uint2& hi, uint2& lo) {
    uint32_t h0, l0, h1, l1;
    split2(v.x, v.y, h0, l0);
    split2(v.z, v.w, h1, l1);
    hi = make_uint2(h0, h1);
    lo = make_uint2(l0, l1);
}

// ---------------- small kernels --------------------------------------------
__global__ void zero_cnt_kernel() {
    if (threadIdx.x < NES) g_cnt[threadIdx.x] = 0;
}

// ---------------- gating + output init -------------------------------------
__global__ __launch_bounds__(256) void gate_kernel(
    const float* __restrict__ x,
    const float* __restrict__ gw, const float* __restrict__ gb,
    const float* __restrict__ shb2, const float* __restrict__ spb2,
    float* __restrict__ wout, float* __restrict__ out)
{
    __shared__ float sgw[ND * NE];
    __shared__ float sgb[NE];
    __shared__ float sbsh[NO];
    __shared__ float sbsp[NES][NO];
    int tid = threadIdx.x;
    for (int i = tid; i < ND * NE; i += 256) sgw[i] = gw[i];
    if (tid < NE) sgb[tid] = gb[tid];
    for (int i = tid; i < NO; i += 256) sbsh[i] = 0.5f * (shb2[i] + shb2[NO + i]);
    for (int q = tid; q < NES * NO; q += 256) sbsp[q / NO][q % NO] = spb2[q];
    __syncthreads();

    int warp = tid >> 5, lane = tid & 31;
    int t = blockIdx.x * 8 + warp;
    const float* xr = x + (size_t)t * ND;
    float acc[NE];
    #pragma unroll
    for (int e = 0; e < NE; e++) acc[e] = 0.f;
    #pragma unroll
    for (int r = 0; r < ND / 32; r++) {
        int d = r * 32 + lane;
        float xv = xr[d];
        const float* g = &sgw[d * NE];
        #pragma unroll
        for (int e = 0; e < NE; e++) acc[e] += xv * g[e];
    }
    #pragma unroll
    for (int e = 0; e < NE; e++) {
        float v = acc[e];
        #pragma unroll
        for (int off = 16; off > 0; off >>= 1) v += __shfl_xor_sync(0xFFFFFFFFu, v, off);
        acc[e] = v + sgb[e];
    }
    float m = acc[0];
    #pragma unroll
    for (int e = 1; e < NE; e++) m = fmaxf(m, acc[e]);
    float s = 0.f, w[NE];
    #pragma unroll
    for (int e = 0; e < NE; e++) { w[e] = expf(acc[e] - m); s += w[e]; }
    float inv = 1.f / s;
    #pragma unroll
    for (int e = 0; e < NE; e++) w[e] *= inv;

    if (lane < NE) wout[(size_t)t * NE + lane] = w[lane];

    int i1 = 0, i2 = -1; float v1 = 0.f, v2 = 0.f;
    if (lane == 0) {
        v1 = w[0];
        #pragma unroll
        for (int e = 1; e < NE; e++) if (w[e] > v1) { v1 = w[e]; i1 = e; }
        v2 = -1.f;
        #pragma unroll
        for (int e = 0; e < NE; e++) if (e != i1 && w[e] > v2) { v2 = w[e]; i2 = e; }
        if (i1 >= NS) {
            int ex = i1 - NS;
            int p = atomicAdd(&g_cnt[ex], 1);
            g_tok[ex * NB + p] = t; g_tw[ex * NB + p] = v1;
        }
        if (i2 >= NS) {
            int ex = i2 - NS;
            int p = atomicAdd(&g_cnt[ex], 1);
            g_tok[ex * NB + p] = t; g_tw[ex * NB + p] = v2;
        }
    }
    i1 = __shfl_sync(0xFFFFFFFFu, i1, 0);
    i2 = __shfl_sync(0xFFFFFFFFu, i2, 0);
    v1 = __shfl_sync(0xFFFFFFFFu, v1, 0);
    v2 = __shfl_sync(0xFFFFFFFFu, v2, 0);

    for (int c = lane; c < NO; c += 32) {
        float val = sbsh[c];
        if (i1 >= NS) val += v1 * sbsp[i1 - NS][c];
        if (i2 >= NS) val += v2 * sbsp[i2 - NS][c];
        out[(size_t)t * NO + c] = val;
    }
}

// ---------------- fused expert tile (HMMA), 64 tokens x 256 out ------------
// Streams original fp32 weights, splits to bf16 hi/lo on the fly.
__device__ __forceinline__ void run_tile(char* dsm, uint32_t sb,
                                         const float* __restrict__ x,
                                         int ge_base, int ge_cnt,
                                         const float* __restrict__ w1f,  // [ge][d][f] fp32 (expert base applied by caller stride)
                                         const float* __restrict__ b1all,
                                         const float* __restrict__ w2f,  // [ge][f][o] fp32
                                         float* __restrict__ out)
{
    int tid = threadIdx.x;
    int wid = tid >> 5, lane = tid & 31;
    int lo16 = lane & 15, hi16 = lane >> 4;
    int* toks = (int*)(dsm + OFF_TOK);
    float* tws = (float*)(dsm + OFF_WT);
    float* b1s = (float*)(dsm + OFF_B1);

    // x tile: 64 rows x 256 fp32, split -> hi/lo. 4096 float4 / 256 thr = 16 iters
    #pragma unroll
    for (int i = 0; i < 16; i++) {
        int q = i * 256 + tid;
        int r = q >> 6, c = q & 63;
        float4 v = *(const float4*)(x + (size_t)toks[r] * ND + c * 4);
        uint2 hi, lo;
        split4(v, hi, lo);
        *(uint2*)(dsm + OFF_XH + r * XSB + c * 8) = hi;
        *(uint2*)(dsm + OFF_XL + r * XSB + c * 8) = lo;
    }

    int wm1 = wid & 3, wn1 = wid >> 2;   // GEMM1: 4x2 warps, 16x32 tiles
    int wm2 = wid & 1, wn2 = wid >> 1;   // GEMM2: 2x4 warps, 32x64 tiles

    float c2[2][8][4];
    #pragma unroll
    for (int mi = 0; mi < 2; mi++)
        #pragma unroll
        for (int ni = 0; ni < 8; ni++)
            #pragma unroll
            for (int r = 0; r < 4; r++) c2[mi][ni][r] = 0.f;

    #pragma unroll 1
    for (int ei = 0; ei < ge_cnt; ei++) {
        int ge = ge_base + ei;
        const float* b1 = b1all + (size_t)ei * NF;

        #pragma unroll 1
        for (int fc = 0; fc < 16; fc++) {
            __syncthreads();
            if (tid < 64) b1s[tid] = b1[fc * 64 + tid];
            float c1[4][4];
            #pragma unroll
            for (int ni = 0; ni < 4; ni++)
                #pragma unroll
                for (int r = 0; r < 4; r++) c1[ni][r] = 0.f;

            // ---- GEMM1: h_chunk[64 x 64] = x[64 x 256] @ W1[:, fc*64..] ----
            #pragma unroll 1
            for (int kg = 0; kg < 4; kg++) {
                __syncthreads();
                // W1 slice [64 rows D x 64 cols F] fp32: 1024 float4 / 256 thr
                #pragma unroll
                for (int i = 0; i < 4; i++) {
                    int q = i * 256 + tid;
                    int r = q >> 4, c = q & 15;
                    float4 v = *(const float4*)(w1f + ((size_t)ge * ND + kg * 64 + r) * NF
                                                + fc * 64 + c * 4);
                    uint2 hi, lo;
                    split4(v, hi, lo);
                    *(uint2*)(dsm + OFF_W1H + r * W1SB + c * 8) = hi;
                    *(uint2*)(dsm + OFF_W1L + r * W1SB + c * 8) = lo;
                }
                __syncthreads();
                #pragma unroll
                for (int ks = 0; ks < 4; ks++) {
                    int k0 = kg * 64 + ks * 16;
                    uint32_t ah[4], al[4];
                    uint32_t arow = (uint32_t)((wm1 * 16 + lo16) * XSB + (k0 + hi16 * 8) * 2);
                    ldsm_x4(ah, sb + OFF_XH + arow);
                    ldsm_x4(al, sb + OFF_XL + arow);
                    #pragma unroll
                    for (int ni = 0; ni < 4; ni++) {
                        int n0 = wn1 * 32 + ni * 8;
                        uint32_t brow = (uint32_t)((ks * 16 + lo16) * W1SB + n0 * 2);
                        uint32_t bh0, bh1, bl0, bl1;
                        ldsm_x2t(bh0, bh1, sb + OFF_W1H + brow);
                        ldsm_x2t(bl0, bl1, sb + OFF_W1L + brow);
                        mma16816(c1[ni], ah, bh0, bh1);
                        mma16816(c1[ni], ah, bl0, bl1);
                        mma16816(c1[ni], al, bh0, bh1);
                    }
                }
            }

            // ---- epilogue: h = split(relu(c1 + b1)) -> smem ----
            __syncthreads();
            #pragma unroll
            for (int ni = 0; ni < 4; ni++) {
                int row = wm1 * 16 + (lane >> 2);
                int col = wn1 * 32 + ni * 8 + (lane & 3) * 2;
                float b0 = b1s[col], b1v = b1s[col + 1];
                float v00 = fmaxf(c1[ni][0] + b0, 0.f);
                float v01 = fmaxf(c1[ni][1] + b1v, 0.f);
                float v10 = fmaxf(c1[ni][2] + b0, 0.f);
                float v11 = fmaxf(c1[ni][3] + b1v, 0.f);
                uint32_t h0, l0, h1, l1;
                split2(v00, v01, h0, l0);
                split2(v10, v11, h1, l1);
                *(uint32_t*)(dsm + OFF_HH + row * HSB + col * 2) = h0;
                *(uint32_t*)(dsm + OFF_HL + row * HSB + col * 2) = l0;
                *(uint32_t*)(dsm + OFF_HH + (row + 8) * HSB + col * 2) = h1;
                *(uint32_t*)(dsm + OFF_HL + (row + 8) * HSB + col * 2) = l1;
            }

            // ---- GEMM2: c2[64 x 256] += h[64 x 64] @ W2[fc*64.., :] ----
            #pragma unroll 1
            for (int kg2 = 0; kg2 < 2; kg2++) {
                __syncthreads();
                // W2 slice [32 rows F x 256 cols O] fp32: 2048 float4 / 256 thr
                #pragma unroll
                for (int i = 0; i < 8; i++) {
                    int q = i * 256 + tid;
                    int r = q >> 6, c = q & 63;
                    float4 v = *(const float4*)(w2f + ((size_t)ge * NF + fc * 64 + kg2 * 32 + r) * NO
                                                + c * 4);
                    uint2 hi, lo;
                    split4(v, hi, lo);
                    *(uint2*)(dsm + OFF_W2H + r * W2SB + c * 8) = hi;
                    *(uint2*)(dsm + OFF_W2L + r * W2SB + c * 8) = lo;
                }
                __syncthreads();
                #pragma unroll
                for (int ks = 0; ks < 2; ks++) {
                    int k0 = kg2 * 32 + ks * 16;
                    uint32_t ah[2][4], al[2][4];
                    #pragma unroll
                    for (int mi = 0; mi < 2; mi++) {
                        uint32_t arow = (uint32_t)((wm2 * 32 + mi * 16 + lo16) * HSB
                                                   + (k0 + hi16 * 8) * 2);
                        ldsm_x4(ah[mi], sb + OFF_HH + arow);
                        ldsm_x4(al[mi], sb + OFF_HL + arow);
                    }
                    #pragma unroll
                    for (int ni = 0; ni < 8; ni++) {
                        int n0 = wn2 * 64 + ni * 8;
                        uint32_t brow = (uint32_t)((ks * 16 + lo16) * W2SB + n0 * 2);
                        uint32_t bh0, bh1, bl0, bl1;
                        ldsm_x2t(bh0, bh1, sb + OFF_W2H + brow);
                        ldsm_x2t(bl0, bl1, sb + OFF_W2L + brow);
                        #pragma unroll
                        for (int mi = 0; mi < 2; mi++) {
                            mma16816(c2[mi][ni], ah[mi], bh0, bh1);
                            mma16816(c2[mi][ni], ah[mi], bl0, bl1);
                            mma16816(c2[mi][ni], al[mi], bh0, bh1);
                        }
                    }
                }
            }
        }
    }

    // ---- final: weighted atomic accumulate ----
    #pragma unroll
    for (int mi = 0; mi < 2; mi++)
        #pragma unroll
        for (int ni = 0; ni < 8; ni++) {
            int row = wm2 * 32 + mi * 16 + (lane >> 2);
            int col = wn2 * 64 + ni * 8 + (lane & 3) * 2;
            int t0 = toks[row];     float w0 = tws[row];
            int t1 = toks[row + 8]; float w1 = tws[row + 8];
            atomicAdd(out + (size_t)t0 * NO + col,     w0 * c2[mi][ni][0]);
            atomicAdd(out + (size_t)t0 * NO + col + 1, w0 * c2[mi][ni][1]);
            atomicAdd(out + (size_t)t1 * NO + col,     w1 * c2[mi][ni][2]);
            atomicAdd(out + (size_t)t1 * NO + col + 1, w1 * c2[mi][ni][3]);
        }
}

// ---------------- expert kernels -------------------------------------------
__global__ __launch_bounds__(256)
void shared_kernel(const float* __restrict__ x,
                   const float* __restrict__ w1f, const float* __restrict__ b1all,
                   const float* __restrict__ w2f, float* __restrict__ out)
{
    extern __shared__ char dsm[];
    int t0 = blockIdx.x * MT;
    int tid = threadIdx.x;
    if (tid < MT) {
        ((int*)(dsm + OFF_TOK))[tid] = t0 + tid;
        ((float*)(dsm + OFF_WT))[tid] = 0.5f;
    }
    __syncthreads();
    uint32_t sb = (uint32_t)__cvta_generic_to_shared(dsm);
    run_tile(dsm, sb, x, 0, NS, w1f, b1all, w2f, out);
}

__global__ __launch_bounds__(256)
void specific_kernel(const float* __restrict__ x,
                     const float* __restrict__ w1f, const float* __restrict__ b1all,
                     const float* __restrict__ w2f, float* __restrict__ out)
{
    int e = blockIdx.y;
    int n = g_cnt[e];
    int base = blockIdx.x * MT;
    if (base >= n) return;
    extern __shared__ char dsm[];
    int tid = threadIdx.x;
    if (tid < MT) {
        int p = base + tid;
        bool ok = (p < n);
        ((int*)(dsm + OFF_TOK))[tid] = ok ? g_tok[e * NB + p] : 0;
        ((float*)(dsm + OFF_WT))[tid] = ok ? g_tw[e * NB + p] : 0.f;
    }
    __syncthreads();
    uint32_t sb = (uint32_t)__cvta_generic_to_shared(dsm);
    // pass expert-local pointers with ge_base=0 so indexing stays in-bounds
    run_tile(dsm, sb, x, 0, 1,
             w1f + (size_t)e * ND * NF,
             b1all + (size_t)e * NF,
             w2f + (size_t)e * NF * NO, out);
}

// ---------------- launch ----------------------------------------------------
extern "C" void kernel_launch(void* const* d_in, const int* in_sizes, int n_in,
                              void* d_out, int out_size)
{
    const float* x      = (const float*)d_in[0];
    const float* gate_w = (const float*)d_in[1];
    const float* gate_b = (const float*)d_in[2];
    const float* sh_w1  = (const float*)d_in[3];
    const float* sh_b1  = (const float*)d_in[4];
    const float* sh_w2  = (const float*)d_in[5];
    const float* sh_b2  = (const float*)d_in[6];
    const float* sp_w1  = (const float*)d_in[7];
    const float* sp_b1  = (const float*)d_in[8];
    const float* sp_w2  = (const float*)d_in[9];
    const float* sp_b2  = (const float*)d_in[10];

    float* out  = (float*)d_out;
    float* wout = out + (size_t)NB * NO;

    cudaFuncSetAttribute(shared_kernel, cudaFuncAttributeMaxDynamicSharedMemorySize, DSM_BYTES);
    cudaFuncSetAttribute(specific_kernel, cudaFuncAttributeMaxDynamicSharedMemorySize, DSM_BYTES);

    zero_cnt_kernel<<<1, 32>>>();
    gate_kernel<<<NB / 8, 256>>>(x, gate_w, gate_b, sh_b2, sp_b2, wout, out);
    shared_kernel<<<NB / MT, 256, DSM_BYTES>>>(x, sh_w1, sh_b1, sh_w2, out);
    specific_kernel<<<dim3(NB / MT, NES), 256, DSM_BYTES>>>(x, sp_w1, sp_b1, sp_w2, out);
}

// round 6
// speedup vs baseline: 1.9553x; 1.1269x over previous
#include <cuda_runtime.h>
#include <cuda_bf16.h>
#include <math.h>
#include <stdint.h>

#define NB 16384
#define ND 256
#define NF 1024
#define NO 256
#define NE 8
#define NS 2
#define NES 6
#define MT 64

// smem row strides in bytes (16B pad keeps ldmatrix conflict-free)
#define XSB  144   // x K-chunk row: 64 bf16 + 8 pad
#define HSB  144
#define W1SB 144
#define W2SB 528

// dynamic smem layout (bytes) — total ~88 KB => 2 CTAs/SM
#define OFF_TOK 0
#define OFF_WT  256
#define OFF_B1  512
#define OFF_XH  768
#define OFF_XL  (OFF_XH + MT * XSB)
#define OFF_HH  (OFF_XL + MT * XSB)
#define OFF_HL  (OFF_HH + MT * HSB)
#define OFF_W1H (OFF_HL + MT * HSB)
#define OFF_W1L (OFF_W1H + 64 * W1SB)
#define OFF_W2H (OFF_W1L + 64 * W1SB)
#define OFF_W2L (OFF_W2H + 32 * W2SB)
#define DSM_BYTES (OFF_W2L + 32 * W2SB)   // 89856

// ---------------- device scratch -------------------------------------------
__device__ int   g_cnt[NES];
__device__ int   g_tok[NES * NB];
__device__ float g_tw [NES * NB];

// ---------------- PTX helpers ----------------------------------------------
__device__ __forceinline__ void ldsm_x4(uint32_t* a, uint32_t addr) {
    asm volatile("ldmatrix.sync.aligned.m8n8.x4.shared.b16 {%0,%1,%2,%3}, [%4];"
                 : "=r"(a[0]), "=r"(a[1]), "=r"(a[2]), "=r"(a[3]) : "r"(addr));
}
__device__ __forceinline__ void ldsm_x2t(uint32_t& b0, uint32_t& b1, uint32_t addr) {
    asm volatile("ldmatrix.sync.aligned.m8n8.x2.trans.shared.b16 {%0,%1}, [%2];"
                 : "=r"(b0), "=r"(b1) : "r"(addr));
}
__device__ __forceinline__ void mma16816(float* c, const uint32_t* a,
                                         uint32_t b0, uint32_t b1) {
    asm volatile(
        "mma.sync.aligned.m16n8k16.row.col.f32.bf16.bf16.f32 "
        "{%0,%1,%2,%3}, {%4,%5,%6,%7}, {%8,%9}, {%0,%1,%2,%3};"
        : "+f"(c[0]), "+f"(c[1]), "+f"(c[2]), "+f"(c[3])
        : "r"(a[0]), "r"(a[1]), "r"(a[2]), "r"(a[3]), "r"(b0), "r"(b1));
}
__device__ __forceinline__ void split2(float a, float b, uint32_t& hi, uint32_t& lo) {
    __nv_bfloat16 ha = __float2bfloat16_rn(a);
    __nv_bfloat16 hb = __float2bfloat16_rn(b);
    __nv_bfloat16 la = __float2bfloat16_rn(a - __bfloat162float(ha));
    __nv_bfloat16 lb = __float2bfloat16_rn(b - __bfloat162float(hb));
    hi = (uint32_t)__bfloat16_as_ushort(ha) | ((uint32_t)__bfloat16_as_ushort(hb) << 16);
    lo = (uint32_t)__bfloat16_as_ushort(la) | ((uint32_t)__bfloat16_as_ushort(lb) << 16);
}
__device__ __forceinline__ void split4(float4 v, uint2& hi, uint2& lo) {
    uint32_t h0, l0, h1, l1;
    split2(v.x, v.y, h0, l0);
    split2(v.z, v.w, h1, l1);
    hi = make_uint2(h0, h1);
    lo = make_uint2(l0, l1);
}

// ---------------- small kernels --------------------------------------------
__global__ void zero_cnt_kernel() {
    if (threadIdx.x < NES) g_cnt[threadIdx.x] = 0;
}

// ---------------- gating + output init -------------------------------------
__global__ __launch_bounds__(256) void gate_kernel(
    const float* __restrict__ x,
    const float* __restrict__ gw, const float* __restrict__ gb,
    const float* __restrict__ shb2, const float* __restrict__ spb2,
    float* __restrict__ wout, float* __restrict__ out)
{
    __shared__ float sgw[ND * NE];
    __shared__ float sgb[NE];
    __shared__ float sbsh[NO];
    __shared__ float sbsp[NES][NO];
    int tid = threadIdx.x;
    for (int i = tid; i < ND * NE; i += 256) sgw[i] = gw[i];
    if (tid < NE) sgb[tid] = gb[tid];
    for (int i = tid; i < NO; i += 256) sbsh[i] = 0.5f * (shb2[i] + shb2[NO + i]);
    for (int q = tid; q < NES * NO; q += 256) sbsp[q / NO][q % NO] = spb2[q];
    __syncthreads();

    int warp = tid >> 5, lane = tid & 31;
    int t = blockIdx.x * 8 + warp;
    const float* xr = x + (size_t)t * ND;
    float acc[NE];
    #pragma unroll
    for (int e = 0; e < NE; e++) acc[e] = 0.f;
    #pragma unroll
    for (int r = 0; r < ND / 32; r++) {
        int d = r * 32 + lane;
        float xv = xr[d];
        const float* g = &sgw[d * NE];
        #pragma unroll
        for (int e = 0; e < NE; e++) acc[e] += xv * g[e];
    }
    #pragma unroll
    for (int e = 0; e < NE; e++) {
        float v = acc[e];
        #pragma unroll
        for (int off = 16; off > 0; off >>= 1) v += __shfl_xor_sync(0xFFFFFFFFu, v, off);
        acc[e] = v + sgb[e];
    }
    float m = acc[0];
    #pragma unroll
    for (int e = 1; e < NE; e++) m = fmaxf(m, acc[e]);
    float s = 0.f, w[NE];
    #pragma unroll
    for (int e = 0; e < NE; e++) { w[e] = expf(acc[e] - m); s += w[e]; }
    float inv = 1.f / s;
    #pragma unroll
    for (int e = 0; e < NE; e++) w[e] *= inv;

    if (lane < NE) wout[(size_t)t * NE + lane] = w[lane];

    int i1 = 0, i2 = -1; float v1 = 0.f, v2 = 0.f;
    if (lane == 0) {
        v1 = w[0];
        #pragma unroll
        for (int e = 1; e < NE; e++) if (w[e] > v1) { v1 = w[e]; i1 = e; }
        v2 = -1.f;
        #pragma unroll
        for (int e = 0; e < NE; e++) if (e != i1 && w[e] > v2) { v2 = w[e]; i2 = e; }
        if (i1 >= NS) {
            int ex = i1 - NS;
            int p = atomicAdd(&g_cnt[ex], 1);
            g_tok[ex * NB + p] = t; g_tw[ex * NB + p] = v1;
        }
        if (i2 >= NS) {
            int ex = i2 - NS;
            int p = atomicAdd(&g_cnt[ex], 1);
            g_tok[ex * NB + p] = t; g_tw[ex * NB + p] = v2;
        }
    }
    i1 = __shfl_sync(0xFFFFFFFFu, i1, 0);
    i2 = __shfl_sync(0xFFFFFFFFu, i2, 0);
    v1 = __shfl_sync(0xFFFFFFFFu, v1, 0);
    v2 = __shfl_sync(0xFFFFFFFFu, v2, 0);

    for (int c = lane; c < NO; c += 32) {
        float val = sbsh[c];
        if (i1 >= NS) val += v1 * sbsp[i1 - NS][c];
        if (i2 >= NS) val += v2 * sbsp[i2 - NS][c];
        out[(size_t)t * NO + c] = val;
    }
}

// ---------------- fused expert tile (HMMA), 64 tokens x 256 out ------------
// Streams x K-chunks + fp32 weights, splits to bf16 hi/lo on the fly.
__device__ __forceinline__ void run_tile(char* dsm, uint32_t sb,
                                         const float* __restrict__ x,
                                         int ge_cnt,
                                         const float* __restrict__ w1f,
                                         const float* __restrict__ b1all,
                                         const float* __restrict__ w2f,
                                         float* __restrict__ out)
{
    int tid = threadIdx.x;
    int wid = tid >> 5, lane = tid & 31;
    int lo16 = lane & 15, hi16 = lane >> 4;
    int* toks = (int*)(dsm + OFF_TOK);
    float* tws = (float*)(dsm + OFF_WT);
    float* b1s = (float*)(dsm + OFF_B1);

    int wm1 = wid & 3, wn1 = wid >> 2;   // GEMM1: 4x2 warps, 16x32 tiles
    int wm2 = wid & 1, wn2 = wid >> 1;   // GEMM2: 2x4 warps, 32x64 tiles

    float c2[2][8][4];
    #pragma unroll
    for (int mi = 0; mi < 2; mi++)
        #pragma unroll
        for (int ni = 0; ni < 8; ni++)
            #pragma unroll
            for (int r = 0; r < 4; r++) c2[mi][ni][r] = 0.f;

    #pragma unroll 1
    for (int ei = 0; ei < ge_cnt; ei++) {
        const float* w1 = w1f + (size_t)ei * ND * NF;
        const float* w2 = w2f + (size_t)ei * NF * NO;
        const float* b1 = b1all + (size_t)ei * NF;

        #pragma unroll 1
        for (int fc = 0; fc < 16; fc++) {
            if (tid < 64) b1s[tid] = b1[fc * 64 + tid];
            float c1[4][4];
            #pragma unroll
            for (int ni = 0; ni < 4; ni++)
                #pragma unroll
                for (int r = 0; r < 4; r++) c1[ni][r] = 0.f;

            // ---- GEMM1: h_chunk[64 x 64] = x[64 x 256] @ W1[:, fc*64..] ----
            #pragma unroll 1
            for (int kg = 0; kg < 4; kg++) {
                __syncthreads();   // previous readers of X/W1 slices done
                // x K-chunk [64 tok x 64 D] fp32 -> hi/lo : 1024 float4
                #pragma unroll
                for (int i = 0; i < 4; i++) {
                    int q = i * 256 + tid;
                    int r = q >> 4, c = q & 15;
                    float4 v = *(const float4*)(x + (size_t)toks[r] * ND + kg * 64 + c * 4);
                    uint2 hi, lo;
                    split4(v, hi, lo);
                    *(uint2*)(dsm + OFF_XH + r * XSB + c * 8) = hi;
                    *(uint2*)(dsm + OFF_XL + r * XSB + c * 8) = lo;
                }
                // W1 slice [64 D x 64 F] fp32 -> hi/lo : 1024 float4
                #pragma unroll
                for (int i = 0; i < 4; i++) {
                    int q = i * 256 + tid;
                    int r = q >> 4, c = q & 15;
                    float4 v = *(const float4*)(w1 + (size_t)(kg * 64 + r) * NF
                                                + fc * 64 + c * 4);
                    uint2 hi, lo;
                    split4(v, hi, lo);
                    *(uint2*)(dsm + OFF_W1H + r * W1SB + c * 8) = hi;
                    *(uint2*)(dsm + OFF_W1L + r * W1SB + c * 8) = lo;
                }
                __syncthreads();
                #pragma unroll
                for (int ks = 0; ks < 4; ks++) {
                    uint32_t ah[4], al[4];
                    uint32_t arow = (uint32_t)((wm1 * 16 + lo16) * XSB
                                               + (ks * 16 + hi16 * 8) * 2);
                    ldsm_x4(ah, sb + OFF_XH + arow);
                    ldsm_x4(al, sb + OFF_XL + arow);
                    #pragma unroll
                    for (int ni = 0; ni < 4; ni++) {
                        int n0 = wn1 * 32 + ni * 8;
                        uint32_t brow = (uint32_t)((ks * 16 + lo16) * W1SB + n0 * 2);
                        uint32_t bh0, bh1, bl0, bl1;
                        ldsm_x2t(bh0, bh1, sb + OFF_W1H + brow);
                        ldsm_x2t(bl0, bl1, sb + OFF_W1L + brow);
                        mma16816(c1[ni], ah, bh0, bh1);
                        mma16816(c1[ni], ah, bl0, bl1);
                        mma16816(c1[ni], al, bh0, bh1);
                    }
                }
            }

            // ---- epilogue: h = split(relu(c1 + b1)) -> smem ----
            // (previous fc's GEMM2 ended with its kg2-loop syncs; H free)
            #pragma unroll
            for (int ni = 0; ni < 4; ni++) {
                int row = wm1 * 16 + (lane >> 2);
                int col = wn1 * 32 + ni * 8 + (lane & 3) * 2;
                float b0 = b1s[col], b1v = b1s[col + 1];
                float v00 = fmaxf(c1[ni][0] + b0, 0.f);
                float v01 = fmaxf(c1[ni][1] + b1v, 0.f);
                float v10 = fmaxf(c1[ni][2] + b0, 0.f);
                float v11 = fmaxf(c1[ni][3] + b1v, 0.f);
                uint32_t h0, l0, h1, l1;
                split2(v00, v01, h0, l0);
                split2(v10, v11, h1, l1);
                *(uint32_t*)(dsm + OFF_HH + row * HSB + col * 2) = h0;
                *(uint32_t*)(dsm + OFF_HL + row * HSB + col * 2) = l0;
                *(uint32_t*)(dsm + OFF_HH + (row + 8) * HSB + col * 2) = h1;
                *(uint32_t*)(dsm + OFF_HL + (row + 8) * HSB + col * 2) = l1;
            }

            // ---- GEMM2: c2[64 x 256] += h[64 x 64] @ W2[fc*64.., :] ----
            #pragma unroll 1
            for (int kg2 = 0; kg2 < 2; kg2++) {
                __syncthreads();   // H visible; previous W2 readers done
                #pragma unroll
                for (int i = 0; i < 8; i++) {   // W2 slice [32 F x 256 O]
                    int q = i * 256 + tid;
                    int r = q >> 6, c = q & 63;
                    float4 v = *(const float4*)(w2 + (size_t)(fc * 64 + kg2 * 32 + r) * NO
                                                + c * 4);
                    uint2 hi, lo;
                    split4(v, hi, lo);
                    *(uint2*)(dsm + OFF_W2H + r * W2SB + c * 8) = hi;
                    *(uint2*)(dsm + OFF_W2L + r * W2SB + c * 8) = lo;
                }
                __syncthreads();
                #pragma unroll
                for (int ks = 0; ks < 2; ks++) {
                    int k0 = kg2 * 32 + ks * 16;
                    uint32_t ah[2][4], al[2][4];
                    #pragma unroll
                    for (int mi = 0; mi < 2; mi++) {
                        uint32_t arow = (uint32_t)((wm2 * 32 + mi * 16 + lo16) * HSB
                                                   + (k0 + hi16 * 8) * 2);
                        ldsm_x4(ah[mi], sb + OFF_HH + arow);
                        ldsm_x4(al[mi], sb + OFF_HL + arow);
                    }
                    #pragma unroll
                    for (int ni = 0; ni < 8; ni++) {
                        int n0 = wn2 * 64 + ni * 8;
                        uint32_t brow = (uint32_t)((ks * 16 + lo16) * W2SB + n0 * 2);
                        uint32_t bh0, bh1, bl0, bl1;
                        ldsm_x2t(bh0, bh1, sb + OFF_W2H + brow);
                        ldsm_x2t(bl0, bl1, sb + OFF_W2L + brow);
                        #pragma unroll
                        for (int mi = 0; mi < 2; mi++) {
                            mma16816(c2[mi][ni], ah[mi], bh0, bh1);
                            mma16816(c2[mi][ni], ah[mi], bl0, bl1);
                            mma16816(c2[mi][ni], al[mi], bh0, bh1);
                        }
                    }
                }
            }
        }
    }

    // ---- final: weighted atomic accumulate ----
    #pragma unroll
    for (int mi = 0; mi < 2; mi++)
        #pragma unroll
        for (int ni = 0; ni < 8; ni++) {
            int row = wm2 * 32 + mi * 16 + (lane >> 2);
            int col = wn2 * 64 + ni * 8 + (lane & 3) * 2;
            int t0 = toks[row];     float w0 = tws[row];
            int t1 = toks[row + 8]; float w1 = tws[row + 8];
            atomicAdd(out + (size_t)t0 * NO + col,     w0 * c2[mi][ni][0]);
            atomicAdd(out + (size_t)t0 * NO + col + 1, w0 * c2[mi][ni][1]);
            atomicAdd(out + (size_t)t1 * NO + col,     w1 * c2[mi][ni][2]);
            atomicAdd(out + (size_t)t1 * NO + col + 1, w1 * c2[mi][ni][3]);
        }
}

// ---------------- expert kernels -------------------------------------------
__global__ __launch_bounds__(256, 2)
void shared_kernel(const float* __restrict__ x,
                   const float* __restrict__ w1f, const float* __restrict__ b1all,
                   const float* __restrict__ w2f, float* __restrict__ out)
{
    extern __shared__ char dsm[];
    int t0 = blockIdx.x * MT;
    int tid = threadIdx.x;
    if (tid < MT) {
        ((int*)(dsm + OFF_TOK))[tid] = t0 + tid;
        ((float*)(dsm + OFF_WT))[tid] = 0.5f;
    }
    __syncthreads();
    uint32_t sb = (uint32_t)__cvta_generic_to_shared(dsm);
    run_tile(dsm, sb, x, NS, w1f, b1all, w2f, out);
}

__global__ __launch_bounds__(256, 2)
void specific_kernel(const float* __restrict__ x,
                     const float* __restrict__ w1f, const float* __restrict__ b1all,
                     const float* __restrict__ w2f, float* __restrict__ out)
{
    int e = blockIdx.y;
    int n = g_cnt[e];
    int base = blockIdx.x * MT;
    if (base >= n) return;
    extern __shared__ char dsm[];
    int tid = threadIdx.x;
    if (tid < MT) {
        int p = base + tid;
        bool ok = (p < n);
        ((int*)(dsm + OFF_TOK))[tid] = ok ? g_tok[e * NB + p] : 0;
        ((float*)(dsm + OFF_WT))[tid] = ok ? g_tw[e * NB + p] : 0.f;
    }
    __syncthreads();
    uint32_t sb = (uint32_t)__cvta_generic_to_shared(dsm);
    run_tile(dsm, sb, x, 1,
             w1f + (size_t)e * ND * NF,
             b1all + (size_t)e * NF,
             w2f + (size_t)e * NF * NO, out);
}

// ---------------- launch ----------------------------------------------------
extern "C" void kernel_launch(void* const* d_in, const int* in_sizes, int n_in,
                              void* d_out, int out_size)
{
    const float* x      = (const float*)d_in[0];
    const float* gate_w = (const float*)d_in[1];
    const float* gate_b = (const float*)d_in[2];
    const float* sh_w1  = (const float*)d_in[3];
    const float* sh_b1  = (const float*)d_in[4];
    const float* sh_w2  = (const float*)d_in[5];
    const float* sh_b2  = (const float*)d_in[6];
    const float* sp_w1  = (const float*)d_in[7];
    const float* sp_b1  = (const float*)d_in[8];
    const float* sp_w2  = (const float*)d_in[9];
    const float* sp_b2  = (const float*)d_in[10];

    float* out  = (float*)d_out;
    float* wout = out + (size_t)NB * NO;

    cudaFuncSetAttribute(shared_kernel, cudaFuncAttributeMaxDynamicSharedMemorySize, DSM_BYTES);
    cudaFuncSetAttribute(specific_kernel, cudaFuncAttributeMaxDynamicSharedMemorySize, DSM_BYTES);

    zero_cnt_kernel<<<1, 32>>>();
    gate_kernel<<<NB / 8, 256>>>(x, gate_w, gate_b, sh_b2, sp_b2, wout, out);
    shared_kernel<<<NB / MT, 256, DSM_BYTES>>>(x, sh_w1, sh_b1, sh_w2, out);
    specific_kernel<<<dim3(NB / MT, NES), 256, DSM_BYTES>>>(x, sp_w1, sp_b1, sp_w2, out);
}

// round 8
// speedup vs baseline: 2.2915x; 1.1719x over previous
#include <cuda_runtime.h>
#include <cuda_bf16.h>
#include <math.h>
#include <stdint.h>

#define NB 16384
#define ND 256
#define NF 1024
#define NO 256
#define NE 8
#define NS 2
#define NES 6
#define MT 128
#define NT 512    // threads per expert CTA

// smem row strides in bytes (16B pad keeps ldmatrix conflict-free)
#define XSB  528   // x row: 256 bf16 + 8 pad
#define HSB  144   // 64 bf16 + 8 pad
#define W1SB 144
#define W2SB 528

// dynamic smem layout (bytes) — total 225536 (~220 KB), 1 CTA/SM
#define OFF_TOK 0
#define OFF_WT  512
#define OFF_B1  1024
#define OFF_XH  1280
#define OFF_XL  (OFF_XH + MT * XSB)
#define OFF_HH  (OFF_XL + MT * XSB)
#define OFF_HL  (OFF_HH + MT * HSB)
#define OFF_W1H (OFF_HL + MT * HSB)
#define OFF_W1L (OFF_W1H + 64 * W1SB)
#define OFF_W2H (OFF_W1L + 64 * W1SB)
#define OFF_W2L (OFF_W2H + 32 * W2SB)
#define DSM_BYTES (OFF_W2L + 32 * W2SB)

// ---------------- device scratch -------------------------------------------
__device__ int   g_cnt[NES];
__device__ int   g_tok[NES * NB];
__device__ float g_tw [NES * NB];

// ---------------- PTX helpers ----------------------------------------------
__device__ __forceinline__ void ldsm_x4(uint32_t* a, uint32_t addr) {
    asm volatile("ldmatrix.sync.aligned.m8n8.x4.shared.b16 {%0,%1,%2,%3}, [%4];"
                 : "=r"(a[0]), "=r"(a[1]), "=r"(a[2]), "=r"(a[3]) : "r"(addr));
}
__device__ __forceinline__ void ldsm_x2t(uint32_t& b0, uint32_t& b1, uint32_t addr) {
    asm volatile("ldmatrix.sync.aligned.m8n8.x2.trans.shared.b16 {%0,%1}, [%2];"
                 : "=r"(b0), "=r"(b1) : "r"(addr));
}
__device__ __forceinline__ void mma16816(float* c, const uint32_t* a,
                                         uint32_t b0, uint32_t b1) {
    asm volatile(
        "mma.sync.aligned.m16n8k16.row.col.f32.bf16.bf16.f32 "
        "{%0,%1,%2,%3}, {%4,%5,%6,%7}, {%8,%9}, {%0,%1,%2,%3};"
        : "+f"(c[0]), "+f"(c[1]), "+f"(c[2]), "+f"(c[3])
        : "r"(a[0]), "r"(a[1]), "r"(a[2]), "r"(a[3]), "r"(b0), "r"(b1));
}
__device__ __forceinline__ void split2(float a, float b, uint32_t& hi, uint32_t& lo) {
    __nv_bfloat16 ha = __float2bfloat16_rn(a);
    __nv_bfloat16 hb = __float2bfloat16_rn(b);
    __nv_bfloat16 la = __float2bfloat16_rn(a - __bfloat162float(ha));
    __nv_bfloat16 lb = __float2bfloat16_rn(b - __bfloat162float(hb));
    hi = (uint32_t)__bfloat16_as_ushort(ha) | ((uint32_t)__bfloat16_as_ushort(hb) << 16);
    lo = (uint32_t)__bfloat16_as_ushort(la) | ((uint32_t)__bfloat16_as_ushort(lb) << 16);
}
__device__ __forceinline__ void split4(float4 v, uint2& hi, uint2& lo) {
    uint32_t h0, l0, h1, l1;
    split2(v.x, v.y, h0, l0);
    split2(v.z, v.w, h1, l1);
    hi = make_uint2(h0, h1);
    lo = make_uint2(l0, l1);
}

// ---------------- small kernels --------------------------------------------
__global__ void zero_cnt_kernel() {
    if (threadIdx.x < NES) g_cnt[threadIdx.x] = 0;
}

// ---------------- gating + output init -------------------------------------
__global__ __launch_bounds__(256) void gate_kernel(
    const float* __restrict__ x,
    const float* __restrict__ gw, const float* __restrict__ gb,
    const float* __restrict__ shb2, const float* __restrict__ spb2,
    float* __restrict__ wout, float* __restrict__ out)
{
    __shared__ float sgw[ND * NE];
    __shared__ float sgb[NE];
    __shared__ float sbsh[NO];
    __shared__ float sbsp[NES][NO];
    int tid = threadIdx.x;
    for (int i = tid; i < ND * NE; i += 256) sgw[i] = gw[i];
    if (tid < NE) sgb[tid] = gb[tid];
    for (int i = tid; i < NO; i += 256) sbsh[i] = 0.5f * (shb2[i] + shb2[NO + i]);
    for (int q = tid; q < NES * NO; q += 256) sbsp[q / NO][q % NO] = spb2[q];
    __syncthreads();

    int warp = tid >> 5, lane = tid & 31;
    int t = blockIdx.x * 8 + warp;
    const float* xr = x + (size_t)t * ND;
    float acc[NE];
    #pragma unroll
    for (int e = 0; e < NE; e++) acc[e] = 0.f;
    #pragma unroll
    for (int r = 0; r < ND / 32; r++) {
        int d = r * 32 + lane;
        float xv = xr[d];
        const float* g = &sgw[d * NE];
        #pragma unroll
        for (int e = 0; e < NE; e++) acc[e] += xv * g[e];
    }
    #pragma unroll
    for (int e = 0; e < NE; e++) {
        float v = acc[e];
        #pragma unroll
        for (int off = 16; off > 0; off >>= 1) v += __shfl_xor_sync(0xFFFFFFFFu, v, off);
        acc[e] = v + sgb[e];
    }
    float m = acc[0];
    #pragma unroll
    for (int e = 1; e < NE; e++) m = fmaxf(m, acc[e]);
    float s = 0.f, w[NE];
    #pragma unroll
    for (int e = 0; e < NE; e++) { w[e] = expf(acc[e] - m); s += w[e]; }
    float inv = 1.f / s;
    #pragma unroll
    for (int e = 0; e < NE; e++) w[e] *= inv;

    if (lane < NE) wout[(size_t)t * NE + lane] = w[lane];

    int i1 = 0, i2 = -1; float v1 = 0.f, v2 = 0.f;
    if (lane == 0) {
        v1 = w[0];
        #pragma unroll
        for (int e = 1; e < NE; e++) if (w[e] > v1) { v1 = w[e]; i1 = e; }
        v2 = -1.f;
        #pragma unroll
        for (int e = 0; e < NE; e++) if (e != i1 && w[e] > v2) { v2 = w[e]; i2 = e; }
        if (i1 >= NS) {
            int ex = i1 - NS;
            int p = atomicAdd(&g_cnt[ex], 1);
            g_tok[ex * NB + p] = t; g_tw[ex * NB + p] = v1;
        }
        if (i2 >= NS) {
            int ex = i2 - NS;
            int p = atomicAdd(&g_cnt[ex], 1);
            g_tok[ex * NB + p] = t; g_tw[ex * NB + p] = v2;
        }
    }
    i1 = __shfl_sync(0xFFFFFFFFu, i1, 0);
    i2 = __shfl_sync(0xFFFFFFFFu, i2, 0);
    v1 = __shfl_sync(0xFFFFFFFFu, v1, 0);
    v2 = __shfl_sync(0xFFFFFFFFu, v2, 0);

    for (int c = lane; c < NO; c += 32) {
        float val = sbsh[c];
        if (i1 >= NS) val += v1 * sbsp[i1 - NS][c];
        if (i2 >= NS) val += v2 * sbsp[i2 - NS][c];
        out[(size_t)t * NO + c] = val;
    }
}

// ---------------- fused expert tile: 128 tokens x 256 out, 512 threads -----
__device__ __forceinline__ void run_tile(char* dsm, uint32_t sb,
                                         const float* __restrict__ x,
                                         int ge_cnt,
                                         const float* __restrict__ w1f,
                                         const float* __restrict__ b1all,
                                         const float* __restrict__ w2f,
                                         float* __restrict__ out)
{
    int tid = threadIdx.x;
    int wid = tid >> 5, lane = tid & 31;
    int lo16 = lane & 15, hi16 = lane >> 4;
    int* toks = (int*)(dsm + OFF_TOK);
    float* tws = (float*)(dsm + OFF_WT);
    float* b1s = (float*)(dsm + OFF_B1);

    // ---- x tile resident: 128 rows x 256 fp32 -> hi/lo bf16 (once) ----
    #pragma unroll
    for (int i = 0; i < 16; i++) {
        int q = i * NT + tid;                 // 8192 float4
        int r = q >> 6, c = q & 63;
        float4 v = *(const float4*)(x + (size_t)toks[r] * ND + c * 4);
        uint2 hi, lo;
        split4(v, hi, lo);
        *(uint2*)(dsm + OFF_XH + r * XSB + c * 8) = hi;
        *(uint2*)(dsm + OFF_XL + r * XSB + c * 8) = lo;
    }

    int wm1 = wid & 7, wn1 = wid >> 3;   // GEMM1: 8x2 warps, 16x32 tiles
    int wm2 = wid & 3, wn2 = wid >> 2;   // GEMM2: 4x4 warps, 32x64 tiles

    // W1 load indices: 1024 float4 / 512 thr = 2 per thread
    int w1r0 = tid >> 4, w1c0 = tid & 15;
    int w1r1 = (tid + NT) >> 4, w1c1 = (tid + NT) & 15;
    // W2 load indices: 2048 float4 / 512 thr = 4 per thread
    int w2r[4], w2c[4];
    #pragma unroll
    for (int i = 0; i < 4; i++) { int q = i * NT + tid; w2r[i] = q >> 6; w2c[i] = q & 63; }

    float c2[2][8][4];
    #pragma unroll
    for (int mi = 0; mi < 2; mi++)
        #pragma unroll
        for (int ni = 0; ni < 8; ni++)
            #pragma unroll
            for (int r = 0; r < 4; r++) c2[mi][ni][r] = 0.f;

    #pragma unroll 1
    for (int ei = 0; ei < ge_cnt; ei++) {
        const float* w1 = w1f + (size_t)ei * ND * NF;
        const float* w2 = w2f + (size_t)ei * NF * NO;
        const float* b1 = b1all + (size_t)ei * NF;

        #pragma unroll 1
        for (int fc = 0; fc < 16; fc++) {
            // b1s written here; first read is in the epilogue below, which is
            // ordered after the kg-loop's __syncthreads() barriers.
            if (tid < 64) b1s[tid] = b1[fc * 64 + tid];
            float c1[4][4];
            #pragma unroll
            for (int ni = 0; ni < 4; ni++)
                #pragma unroll
                for (int r = 0; r < 4; r++) c1[ni][r] = 0.f;

            // ---- GEMM1 with W1 register-prefetch pipeline ----
            float4 pf0 = *(const float4*)(w1 + (size_t)w1r0 * NF + fc * 64 + w1c0 * 4);
            float4 pf1 = *(const float4*)(w1 + (size_t)w1r1 * NF + fc * 64 + w1c1 * 4);
            #pragma unroll 1
            for (int kg = 0; kg < 4; kg++) {
                __syncthreads();   // W1 buffer free (prev MMA done)
                {
                    uint2 hi, lo;
                    split4(pf0, hi, lo);
                    *(uint2*)(dsm + OFF_W1H + w1r0 * W1SB + w1c0 * 8) = hi;
                    *(uint2*)(dsm + OFF_W1L + w1r0 * W1SB + w1c0 * 8) = lo;
                    split4(pf1, hi, lo);
                    *(uint2*)(dsm + OFF_W1H + w1r1 * W1SB + w1c1 * 8) = hi;
                    *(uint2*)(dsm + OFF_W1L + w1r1 * W1SB + w1c1 * 8) = lo;
                }
                if (kg < 3) {      // prefetch next slice; LDG latency hidden by MMA below
                    pf0 = *(const float4*)(w1 + (size_t)((kg + 1) * 64 + w1r0) * NF + fc * 64 + w1c0 * 4);
                    pf1 = *(const float4*)(w1 + (size_t)((kg + 1) * 64 + w1r1) * NF + fc * 64 + w1c1 * 4);
                }
                __syncthreads();
                #pragma unroll
                for (int ks = 0; ks < 4; ks++) {
                    uint32_t ah[4], al[4];
                    uint32_t arow = (uint32_t)((wm1 * 16 + lo16) * XSB
                                               + (kg * 64 + ks * 16 + hi16 * 8) * 2);
                    ldsm_x4(ah, sb + OFF_XH + arow);
                    ldsm_x4(al, sb + OFF_XL + arow);
                    #pragma unroll
                    for (int ni = 0; ni < 4; ni++) {
                        int n0 = wn1 * 32 + ni * 8;
                        uint32_t brow = (uint32_t)((ks * 16 + lo16) * W1SB + n0 * 2);
                        uint32_t bh0, bh1, bl0, bl1;
                        ldsm_x2t(bh0, bh1, sb + OFF_W1H + brow);
                        ldsm_x2t(bl0, bl1, sb + OFF_W1L + brow);
                        mma16816(c1[ni], ah, bh0, bh1);
                        mma16816(c1[ni], ah, bl0, bl1);
                        mma16816(c1[ni], al, bh0, bh1);
                    }
                }
            }

            // ---- epilogue: h = split(relu(c1 + b1)) -> smem ----
            // (H free: previous fc's GEMM2 readers passed kg-loop syncs above)
            #pragma unroll
            for (int ni = 0; ni < 4; ni++) {
                int row = wm1 * 16 + (lane >> 2);
                int col = wn1 * 32 + ni * 8 + (lane & 3) * 2;
                float b0 = b1s[col], b1v = b1s[col + 1];
                float v00 = fmaxf(c1[ni][0] + b0, 0.f);
                float v01 = fmaxf(c1[ni][1] + b1v, 0.f);
                float v10 = fmaxf(c1[ni][2] + b0, 0.f);
                float v11 = fmaxf(c1[ni][3] + b1v, 0.f);
                uint32_t h0, l0, h1, l1;
                split2(v00, v01, h0, l0);
                split2(v10, v11, h1, l1);
                *(uint32_t*)(dsm + OFF_HH + row * HSB + col * 2) = h0;
                *(uint32_t*)(dsm + OFF_HL + row * HSB + col * 2) = l0;
                *(uint32_t*)(dsm + OFF_HH + (row + 8) * HSB + col * 2) = h1;
                *(uint32_t*)(dsm + OFF_HL + (row + 8) * HSB + col * 2) = l1;
            }

            // ---- GEMM2 with W2 register-prefetch pipeline ----
            float4 pw[4];
            #pragma unroll
            for (int i = 0; i < 4; i++)
                pw[i] = *(const float4*)(w2 + (size_t)(fc * 64 + w2r[i]) * NO + w2c[i] * 4);
            #pragma unroll 1
            for (int kg2 = 0; kg2 < 2; kg2++) {
                __syncthreads();   // H writes visible; previous W2 readers done
                #pragma unroll
                for (int i = 0; i < 4; i++) {
                    uint2 hi, lo;
                    split4(pw[i], hi, lo);
                    *(uint2*)(dsm + OFF_W2H + w2r[i] * W2SB + w2c[i] * 8) = hi;
                    *(uint2*)(dsm + OFF_W2L + w2r[i] * W2SB + w2c[i] * 8) = lo;
                }
                if (kg2 == 0) {
                    #pragma unroll
                    for (int i = 0; i < 4; i++)
                        pw[i] = *(const float4*)(w2 + (size_t)(fc * 64 + 32 + w2r[i]) * NO + w2c[i] * 4);
                }
                __syncthreads();
                #pragma unroll
                for (int ks = 0; ks < 2; ks++) {
                    int k0 = kg2 * 32 + ks * 16;
                    uint32_t ah[2][4], al[2][4];
                    #pragma unroll
                    for (int mi = 0; mi < 2; mi++) {
                        uint32_t arow = (uint32_t)((wm2 * 32 + mi * 16 + lo16) * HSB
                                                   + (k0 + hi16 * 8) * 2);
                        ldsm_x4(ah[mi], sb + OFF_HH + arow);
                        ldsm_x4(al[mi], sb + OFF_HL + arow);
                    }
                    #pragma unroll
                    for (int ni = 0; ni < 8; ni++) {
                        int n0 = wn2 * 64 + ni * 8;
                        uint32_t brow = (uint32_t)((ks * 16 + lo16) * W2SB + n0 * 2);
                        uint32_t bh0, bh1, bl0, bl1;
                        ldsm_x2t(bh0, bh1, sb + OFF_W2H + brow);
                        ldsm_x2t(bl0, bl1, sb + OFF_W2L + brow);
                        #pragma unroll
                        for (int mi = 0; mi < 2; mi++) {
                            mma16816(c2[mi][ni], ah[mi], bh0, bh1);
                            mma16816(c2[mi][ni], ah[mi], bl0, bl1);
                            mma16816(c2[mi][ni], al[mi], bh0, bh1);
                        }
                    }
                }
            }
        }
    }

    // ---- final: weighted atomic accumulate ----
    #pragma unroll
    for (int mi = 0; mi < 2; mi++)
        #pragma unroll
        for (int ni = 0; ni < 8; ni++) {
            int row = wm2 * 32 + mi * 16 + (lane >> 2);
            int col = wn2 * 64 + ni * 8 + (lane & 3) * 2;
            int t0 = toks[row];     float w0 = tws[row];
            int t1 = toks[row + 8]; float w1 = tws[row + 8];
            atomicAdd(out + (size_t)t0 * NO + col,     w0 * c2[mi][ni][0]);
            atomicAdd(out + (size_t)t0 * NO + col + 1, w0 * c2[mi][ni][1]);
            atomicAdd(out + (size_t)t1 * NO + col,     w1 * c2[mi][ni][2]);
            atomicAdd(out + (size_t)t1 * NO + col + 1, w1 * c2[mi][ni][3]);
        }
}

// ---------------- expert kernels -------------------------------------------
__global__ __launch_bounds__(NT, 1)
void shared_kernel(const float* __restrict__ x,
                   const float* __restrict__ w1f, const float* __restrict__ b1all,
                   const float* __restrict__ w2f, float* __restrict__ out)
{
    extern __shared__ char dsm[];
    int t0 = blockIdx.x * MT;
    int tid = threadIdx.x;
    if (tid < MT) {
        ((int*)(dsm + OFF_TOK))[tid] = t0 + tid;
        ((float*)(dsm + OFF_WT))[tid] = 0.5f;
    }
    __syncthreads();
    uint32_t sb = (uint32_t)__cvta_generic_to_shared(dsm);
    run_tile(dsm, sb, x, NS, w1f, b1all, w2f, out);
}

__global__ __launch_bounds__(NT, 1)
void specific_kernel(const float* __restrict__ x,
                     const float* __restrict__ w1f, const float* __restrict__ b1all,
                     const float* __restrict__ w2f, float* __restrict__ out)
{
    int e = blockIdx.y;
    int n = g_cnt[e];
    int base = blockIdx.x * MT;
    if (base >= n) return;
    extern __shared__ char dsm[];
    int tid = threadIdx.x;
    if (tid < MT) {
        int p = base + tid;
        bool ok = (p < n);
        ((int*)(dsm + OFF_TOK))[tid] = ok ? g_tok[e * NB + p] : 0;
        ((float*)(dsm + OFF_WT))[tid] = ok ? g_tw[e * NB + p] : 0.f;
    }
    __syncthreads();
    uint32_t sb = (uint32_t)__cvta_generic_to_shared(dsm);
    run_tile(dsm, sb, x, 1,
             w1f + (size_t)e * ND * NF,
             b1all + (size_t)e * NF,
             w2f + (size_t)e * NF * NO, out);
}

// ---------------- launch ----------------------------------------------------
extern "C" void kernel_launch(void* const* d_in, const int* in_sizes, int n_in,
                              void* d_out, int out_size)
{
    const float* x      = (const float*)d_in[0];
    const float* gate_w = (const float*)d_in[1];
    const float* gate_b = (const float*)d_in[2];
    const float* sh_w1  = (const float*)d_in[3];
    const float* sh_b1  = (const float*)d_in[4];
    const float* sh_w2  = (const float*)d_in[5];
    const float* sh_b2  = (const float*)d_in[6];
    const float* sp_w1  = (const float*)d_in[7];
    const float* sp_b1  = (const float*)d_in[8];
    const float* sp_w2  = (const float*)d_in[9];
    const float* sp_b2  = (const float*)d_in[10];

    float* out  = (float*)d_out;
    float* wout = out + (size_t)NB * NO;

    cudaFuncSetAttribute(shared_kernel, cudaFuncAttributeMaxDynamicSharedMemorySize, DSM_BYTES);
    cudaFuncSetAttribute(specific_kernel, cudaFuncAttributeMaxDynamicSharedMemorySize, DSM_BYTES);

    zero_cnt_kernel<<<1, 32>>>();
    gate_kernel<<<NB / 8, 256>>>(x, gate_w, gate_b, sh_b2, sp_b2, wout, out);
    shared_kernel<<<NB / MT, NT, DSM_BYTES>>>(x, sh_w1, sh_b1, sh_w2, out);
    specific_kernel<<<dim3(NB / MT, NES), NT, DSM_BYTES>>>(x, sp_w1, sp_b1, sp_w2, out);
}

// round 9
// speedup vs baseline: 2.5652x; 1.1194x over previous
#include <cuda_runtime.h>
#include <cuda_bf16.h>
#include <math.h>
#include <stdint.h>

#define NB 16384
#define ND 256
#define NF 1024
#define NO 256
#define NE 8
#define NS 2
#define NES 6
#define MT 128
#define NT 512

// smem row strides in bytes (16B pad keeps ldmatrix conflict-free)
#define XSB  528
#define HSB  144
#define W1SB 144
#define W2SB 528

// W chunk buffer sizes
#define W1CH (32 * W1SB)   // 4608: one 32-row hi (or lo) chunk
#define W2CH (16 * W2SB)   // 8448: one 16-row hi (or lo) chunk

// dynamic smem layout (bytes) — total 225536, 1 CTA/SM
#define OFF_TOK 0
#define OFF_WT  512
#define OFF_B1  1024
#define OFF_XH  1280
#define OFF_XL  (OFF_XH + MT * XSB)
#define OFF_HH  (OFF_XL + MT * XSB)
#define OFF_HL  (OFF_HH + MT * HSB)
#define OFF_W1  (OFF_HL + MT * HSB)          // [buf0H, buf0L, buf1H, buf1L]
#define OFF_W2  (OFF_W1 + 4 * W1CH)          // [buf0H, buf0L, buf1H, buf1L]
#define DSM_BYTES (OFF_W2 + 4 * W2CH)

// ---------------- device scratch -------------------------------------------
__device__ int   g_cnt[NES];
__device__ int   g_tok[NES * NB];
__device__ float g_tw [NES * NB];

// ---------------- PTX helpers ----------------------------------------------
__device__ __forceinline__ void ldsm_x4(uint32_t* a, uint32_t addr) {
    asm volatile("ldmatrix.sync.aligned.m8n8.x4.shared.b16 {%0,%1,%2,%3}, [%4];"
                 : "=r"(a[0]), "=r"(a[1]), "=r"(a[2]), "=r"(a[3]) : "r"(addr));
}
__device__ __forceinline__ void ldsm_x4t(uint32_t* b, uint32_t addr) {
    asm volatile("ldmatrix.sync.aligned.m8n8.x4.trans.shared.b16 {%0,%1,%2,%3}, [%4];"
                 : "=r"(b[0]), "=r"(b[1]), "=r"(b[2]), "=r"(b[3]) : "r"(addr));
}
__device__ __forceinline__ void mma16816(float* c, const uint32_t* a,
                                         uint32_t b0, uint32_t b1) {
    asm volatile(
        "mma.sync.aligned.m16n8k16.row.col.f32.bf16.bf16.f32 "
        "{%0,%1,%2,%3}, {%4,%5,%6,%7}, {%8,%9}, {%0,%1,%2,%3};"
        : "+f"(c[0]), "+f"(c[1]), "+f"(c[2]), "+f"(c[3])
        : "r"(a[0]), "r"(a[1]), "r"(a[2]), "r"(a[3]), "r"(b0), "r"(b1));
}
__device__ __forceinline__ void split2(float a, float b, uint32_t& hi, uint32_t& lo) {
    __nv_bfloat16 ha = __float2bfloat16_rn(a);
    __nv_bfloat16 hb = __float2bfloat16_rn(b);
    __nv_bfloat16 la = __float2bfloat16_rn(a - __bfloat162float(ha));
    __nv_bfloat16 lb = __float2bfloat16_rn(b - __bfloat162float(hb));
    hi = (uint32_t)__bfloat16_as_ushort(ha) | ((uint32_t)__bfloat16_as_ushort(hb) << 16);
    lo = (uint32_t)__bfloat16_as_ushort(la) | ((uint32_t)__bfloat16_as_ushort(lb) << 16);
}
__device__ __forceinline__ void split4(float4 v, uint2& hi, uint2& lo) {
    uint32_t h0, l0, h1, l1;
    split2(v.x, v.y, h0, l0);
    split2(v.z, v.w, h1, l1);
    hi = make_uint2(h0, h1);
    lo = make_uint2(l0, l1);
}

// ---------------- small kernels --------------------------------------------
__global__ void zero_cnt_kernel() {
    if (threadIdx.x < NES) g_cnt[threadIdx.x] = 0;
}

// ---------------- gating + output init -------------------------------------
__global__ __launch_bounds__(256) void gate_kernel(
    const float* __restrict__ x,
    const float* __restrict__ gw, const float* __restrict__ gb,
    const float* __restrict__ shb2, const float* __restrict__ spb2,
    float* __restrict__ wout, float* __restrict__ out)
{
    __shared__ float sgw[ND * NE];
    __shared__ float sgb[NE];
    __shared__ float sbsh[NO];
    __shared__ float sbsp[NES][NO];
    int tid = threadIdx.x;
    for (int i = tid; i < ND * NE; i += 256) sgw[i] = gw[i];
    if (tid < NE) sgb[tid] = gb[tid];
    for (int i = tid; i < NO; i += 256) sbsh[i] = 0.5f * (shb2[i] + shb2[NO + i]);
    for (int q = tid; q < NES * NO; q += 256) sbsp[q / NO][q % NO] = spb2[q];
    __syncthreads();

    int warp = tid >> 5, lane = tid & 31;
    int t = blockIdx.x * 8 + warp;
    const float* xr = x + (size_t)t * ND;
    float acc[NE];
    #pragma unroll
    for (int e = 0; e < NE; e++) acc[e] = 0.f;
    #pragma unroll
    for (int r = 0; r < ND / 32; r++) {
        int d = r * 32 + lane;
        float xv = xr[d];
        const float* g = &sgw[d * NE];
        #pragma unroll
        for (int e = 0; e < NE; e++) acc[e] += xv * g[e];
    }
    #pragma unroll
    for (int e = 0; e < NE; e++) {
        float v = acc[e];
        #pragma unroll
        for (int off = 16; off > 0; off >>= 1) v += __shfl_xor_sync(0xFFFFFFFFu, v, off);
        acc[e] = v + sgb[e];
    }
    float m = acc[0];
    #pragma unroll
    for (int e = 1; e < NE; e++) m = fmaxf(m, acc[e]);
    float s = 0.f, w[NE];
    #pragma unroll
    for (int e = 0; e < NE; e++) { w[e] = expf(acc[e] - m); s += w[e]; }
    float inv = 1.f / s;
    #pragma unroll
    for (int e = 0; e < NE; e++) w[e] *= inv;

    if (lane < NE) wout[(size_t)t * NE + lane] = w[lane];

    int i1 = 0, i2 = -1; float v1 = 0.f, v2 = 0.f;
    if (lane == 0) {
        v1 = w[0];
        #pragma unroll
        for (int e = 1; e < NE; e++) if (w[e] > v1) { v1 = w[e]; i1 = e; }
        v2 = -1.f;
        #pragma unroll
        for (int e = 0; e < NE; e++) if (e != i1 && w[e] > v2) { v2 = w[e]; i2 = e; }
        if (i1 >= NS) {
            int ex = i1 - NS;
            int p = atomicAdd(&g_cnt[ex], 1);
            g_tok[ex * NB + p] = t; g_tw[ex * NB + p] = v1;
        }
        if (i2 >= NS) {
            int ex = i2 - NS;
            int p = atomicAdd(&g_cnt[ex], 1);
            g_tok[ex * NB + p] = t; g_tw[ex * NB + p] = v2;
        }
    }
    i1 = __shfl_sync(0xFFFFFFFFu, i1, 0);
    i2 = __shfl_sync(0xFFFFFFFFu, i2, 0);
    v1 = __shfl_sync(0xFFFFFFFFu, v1, 0);
    v2 = __shfl_sync(0xFFFFFFFFu, v2, 0);

    for (int c = lane; c < NO; c += 32) {
        float val = sbsh[c];
        if (i1 >= NS) val += v1 * sbsp[i1 - NS][c];
        if (i2 >= NS) val += v2 * sbsp[i2 - NS][c];
        out[(size_t)t * NO + c] = val;
    }
}

// ---------------- fused expert tile: 128 tokens x 256 out, 512 threads -----
// Ping-pong W buffers: phase = { sync; STS(c+1); LDG(c+2); MMA(c) }.
__device__ __forceinline__ void run_tile(char* dsm, uint32_t sb,
                                         const float* __restrict__ x,
                                         int ge_cnt,
                                         const float* __restrict__ w1f,
                                         const float* __restrict__ b1all,
                                         const float* __restrict__ w2f,
                                         float* __restrict__ out)
{
    int tid = threadIdx.x;
    int wid = tid >> 5, lane = tid & 31;
    int lo16 = lane & 15, hi16 = lane >> 4;
    int* toks = (int*)(dsm + OFF_TOK);
    float* tws = (float*)(dsm + OFF_WT);
    float* b1s = (float*)(dsm + OFF_B1);

    // ---- x tile resident: 128 rows x 256 fp32 -> hi/lo bf16 (once) ----
    #pragma unroll
    for (int i = 0; i < 16; i++) {
        int q = i * NT + tid;
        int r = q >> 6, c = q & 63;
        float4 v = *(const float4*)(x + (size_t)toks[r] * ND + c * 4);
        uint2 hi, lo;
        split4(v, hi, lo);
        *(uint2*)(dsm + OFF_XH + r * XSB + c * 8) = hi;
        *(uint2*)(dsm + OFF_XL + r * XSB + c * 8) = lo;
    }

    int wm1 = wid & 7, wn1 = wid >> 3;   // GEMM1: 8x2 warps, 16x32 tiles
    int wm2 = wid & 3, wn2 = wid >> 2;   // GEMM2: 4x4 warps, 32x64 tiles

    // W1 chunk: 32 rows x 64 cols fp32 = 512 float4, 1 per thread
    int w1r = tid >> 4, w1c = tid & 15;
    // W2 chunk: 16 rows x 256 cols = 1024 float4, 2 per thread
    int w2r0 = tid >> 6,          w2c0 = tid & 63;
    int w2r1 = (tid + NT) >> 6,   w2c1 = (tid + NT) & 63;

    float c2[2][8][4];
    #pragma unroll
    for (int mi = 0; mi < 2; mi++)
        #pragma unroll
        for (int ni = 0; ni < 8; ni++)
            #pragma unroll
            for (int r = 0; r < 4; r++) c2[mi][ni][r] = 0.f;

    #pragma unroll 1
    for (int ei = 0; ei < ge_cnt; ei++) {
        const float* w1 = w1f + (size_t)ei * ND * NF;
        const float* w2 = w2f + (size_t)ei * NF * NO;
        const float* b1 = b1all + (size_t)ei * NF;

        #pragma unroll 1
        for (int fc = 0; fc < 16; fc++) {
            if (tid < 64) b1s[tid] = b1[fc * 64 + tid];
            float c1[4][4];
            #pragma unroll
            for (int ni = 0; ni < 4; ni++)
                #pragma unroll
                for (int r = 0; r < 4; r++) c1[ni][r] = 0.f;

            // ================= GEMM1: 8 chunks of 32 K-rows ================
            float4 pf = *(const float4*)(w1 + (size_t)w1r * NF + fc * 64 + w1c * 4); // chunk 0
            {   // stage chunk 0 (buf0 free: last readers finished a fc ago)
                uint2 hi, lo;
                split4(pf, hi, lo);
                *(uint2*)(dsm + OFF_W1 + w1r * W1SB + w1c * 8) = hi;
                *(uint2*)(dsm + OFF_W1 + W1CH + w1r * W1SB + w1c * 8) = lo;
                pf = *(const float4*)(w1 + (size_t)(32 + w1r) * NF + fc * 64 + w1c * 4); // chunk 1
            }
            #pragma unroll
            for (int c = 0; c < 8; c++) {
                __syncthreads();
                if (c < 7) {  // stage chunk c+1 into the other buffer
                    uint32_t bo = OFF_W1 + ((c + 1) & 1) * (2 * W1CH);
                    uint2 hi, lo;
                    split4(pf, hi, lo);
                    *(uint2*)(dsm + bo + w1r * W1SB + w1c * 8) = hi;
                    *(uint2*)(dsm + bo + W1CH + w1r * W1SB + w1c * 8) = lo;
                }
                if (c < 6)
                    pf = *(const float4*)(w1 + (size_t)((c + 2) * 32 + w1r) * NF + fc * 64 + w1c * 4);
                // MMA on chunk c
                uint32_t bH = OFF_W1 + (c & 1) * (2 * W1CH);
                uint32_t bL = bH + W1CH;
                #pragma unroll
                for (int ks2 = 0; ks2 < 2; ks2++) {
                    int kk = c * 32 + ks2 * 16;
                    uint32_t ah[4], al[4];
                    uint32_t arow = (uint32_t)((wm1 * 16 + lo16) * XSB + (kk + hi16 * 8) * 2);
                    ldsm_x4(ah, sb + OFF_XH + arow);
                    ldsm_x4(al, sb + OFF_XL + arow);
                    #pragma unroll
                    for (int np = 0; np < 2; np++) {
                        int n0 = wn1 * 32 + np * 16;
                        uint32_t brow = (uint32_t)((ks2 * 16 + lo16) * W1SB + (n0 + hi16 * 8) * 2);
                        uint32_t bh[4], bl[4];
                        ldsm_x4t(bh, sb + bH + brow);
                        ldsm_x4t(bl, sb + bL + brow);
                        mma16816(c1[np * 2],     ah, bh[0], bh[1]);
                        mma16816(c1[np * 2],     ah, bl[0], bl[1]);
                        mma16816(c1[np * 2],     al, bh[0], bh[1]);
                        mma16816(c1[np * 2 + 1], ah, bh[2], bh[3]);
                        mma16816(c1[np * 2 + 1], ah, bl[2], bl[3]);
                        mma16816(c1[np * 2 + 1], al, bh[2], bh[3]);
                    }
                }
            }

            // ---- issue W2 chunk0 LDG early; epilogue hides its latency ----
            float4 pw0 = *(const float4*)(w2 + (size_t)(fc * 64 + w2r0) * NO + w2c0 * 4);
            float4 pw1 = *(const float4*)(w2 + (size_t)(fc * 64 + w2r1) * NO + w2c1 * 4);

            // ---- epilogue: h = split(relu(c1 + b1)) -> H smem ----
            // (H free: previous fc's GEMM2 readers are ≥8 syncs behind)
            #pragma unroll
            for (int ni = 0; ni < 4; ni++) {
                int row = wm1 * 16 + (lane >> 2);
                int col = wn1 * 32 + ni * 8 + (lane & 3) * 2;
                float b0 = b1s[col], b1v = b1s[col + 1];
                float v00 = fmaxf(c1[ni][0] + b0, 0.f);
                float v01 = fmaxf(c1[ni][1] + b1v, 0.f);
                float v10 = fmaxf(c1[ni][2] + b0, 0.f);
                float v11 = fmaxf(c1[ni][3] + b1v, 0.f);
                uint32_t h0, l0, h1, l1;
                split2(v00, v01, h0, l0);
                split2(v10, v11, h1, l1);
                *(uint32_t*)(dsm + OFF_HH + row * HSB + col * 2) = h0;
                *(uint32_t*)(dsm + OFF_HL + row * HSB + col * 2) = l0;
                *(uint32_t*)(dsm + OFF_HH + (row + 8) * HSB + col * 2) = h1;
                *(uint32_t*)(dsm + OFF_HL + (row + 8) * HSB + col * 2) = l1;
            }

            // ================= GEMM2: 4 chunks of 16 K-rows ================
            {   // stage chunk 0 (buf0 free since previous fc)
                uint2 hi, lo;
                split4(pw0, hi, lo);
                *(uint2*)(dsm + OFF_W2 + w2r0 * W2SB + w2c0 * 8) = hi;
                *(uint2*)(dsm + OFF_W2 + W2CH + w2r0 * W2SB + w2c0 * 8) = lo;
                split4(pw1, hi, lo);
                *(uint2*)(dsm + OFF_W2 + w2r1 * W2SB + w2c1 * 8) = hi;
                *(uint2*)(dsm + OFF_W2 + W2CH + w2r1 * W2SB + w2c1 * 8) = lo;
                pw0 = *(const float4*)(w2 + (size_t)(fc * 64 + 16 + w2r0) * NO + w2c0 * 4);
                pw1 = *(const float4*)(w2 + (size_t)(fc * 64 + 16 + w2r1) * NO + w2c1 * 4);
            }
            #pragma unroll
            for (int c = 0; c < 4; c++) {
                __syncthreads();   // phase-0 sync also publishes H + W2 chunk0
                if (c < 3) {
                    uint32_t bo = OFF_W2 + ((c + 1) & 1) * (2 * W2CH);
                    uint2 hi, lo;
                    split4(pw0, hi, lo);
                    *(uint2*)(dsm + bo + w2r0 * W2SB + w2c0 * 8) = hi;
                    *(uint2*)(dsm + bo + W2CH + w2r0 * W2SB + w2c0 * 8) = lo;
                    split4(pw1, hi, lo);
                    *(uint2*)(dsm + bo + w2r1 * W2SB + w2c1 * 8) = hi;
                    *(uint2*)(dsm + bo + W2CH + w2r1 * W2SB + w2c1 * 8) = lo;
                }
                if (c < 2) {
                    pw0 = *(const float4*)(w2 + (size_t)(fc * 64 + (c + 2) * 16 + w2r0) * NO + w2c0 * 4);
                    pw1 = *(const float4*)(w2 + (size_t)(fc * 64 + (c + 2) * 16 + w2r1) * NO + w2c1 * 4);
                }
                // MMA on chunk c (16 K-rows = one k-step)
                uint32_t bH = OFF_W2 + (c & 1) * (2 * W2CH);
                uint32_t bL = bH + W2CH;
                uint32_t ah[2][4], al[2][4];
                #pragma unroll
                for (int mi = 0; mi < 2; mi++) {
                    uint32_t arow = (uint32_t)((wm2 * 32 + mi * 16 + lo16) * HSB
                                               + (c * 16 + hi16 * 8) * 2);
                    ldsm_x4(ah[mi], sb + OFF_HH + arow);
                    ldsm_x4(al[mi], sb + OFF_HL + arow);
                }
                #pragma unroll
                for (int np = 0; np < 4; np++) {
                    int n0 = wn2 * 64 + np * 16;
                    uint32_t brow = (uint32_t)(lo16 * W2SB + (n0 + hi16 * 8) * 2);
                    uint32_t bh[4], bl[4];
                    ldsm_x4t(bh, sb + bH + brow);
                    ldsm_x4t(bl, sb + bL + brow);
                    #pragma unroll
                    for (int mi = 0; mi < 2; mi++) {
                        mma16816(c2[mi][np * 2],     ah[mi], bh[0], bh[1]);
                        mma16816(c2[mi][np * 2],     ah[mi], bl[0], bl[1]);
                        mma16816(c2[mi][np * 2],     al[mi], bh[0], bh[1]);
                        mma16816(c2[mi][np * 2 + 1], ah[mi], bh[2], bh[3]);
                        mma16816(c2[mi][np * 2 + 1], ah[mi], bl[2], bl[3]);
                        mma16816(c2[mi][np * 2 + 1], al[mi], bh[2], bh[3]);
                    }
                }
            }
        }
    }

    // ---- final: weighted atomic accumulate ----
    #pragma unroll
    for (int mi = 0; mi < 2; mi++)
        #pragma unroll
        for (int ni = 0; ni < 8; ni++) {
            int row = wm2 * 32 + mi * 16 + (lane >> 2);
            int col = wn2 * 64 + ni * 8 + (lane & 3) * 2;
            int t0 = toks[row];     float w0 = tws[row];
            int t1 = toks[row + 8]; float w1 = tws[row + 8];
            atomicAdd(out + (size_t)t0 * NO + col,     w0 * c2[mi][ni][0]);
            atomicAdd(out + (size_t)t0 * NO + col + 1, w0 * c2[mi][ni][1]);
            atomicAdd(out + (size_t)t1 * NO + col,     w1 * c2[mi][ni][2]);
            atomicAdd(out + (size_t)t1 * NO + col + 1, w1 * c2[mi][ni][3]);
        }
}

// ---------------- expert kernels -------------------------------------------
__global__ __launch_bounds__(NT, 1)
void shared_kernel(const float* __restrict__ x,
                   const float* __restrict__ w1f, const float* __restrict__ b1all,
                   const float* __restrict__ w2f, float* __restrict__ out)
{
    extern __shared__ char dsm[];
    int t0 = blockIdx.x * MT;
    int tid = threadIdx.x;
    if (tid < MT) {
        ((int*)(dsm + OFF_TOK))[tid] = t0 + tid;
        ((float*)(dsm + OFF_WT))[tid] = 0.5f;
    }
    __syncthreads();
    uint32_t sb = (uint32_t)__cvta_generic_to_shared(dsm);
    run_tile(dsm, sb, x, NS, w1f, b1all, w2f, out);
}

__global__ __launch_bounds__(NT, 1)
void specific_kernel(const float* __restrict__ x,
                     const float* __restrict__ w1f, const float* __restrict__ b1all,
                     const float* __restrict__ w2f, float* __restrict__ out)
{
    int e = blockIdx.y;
    int n = g_cnt[e];
    int base = blockIdx.x * MT;
    if (base >= n) return;
    extern __shared__ char dsm[];
    int tid = threadIdx.x;
    if (tid < MT) {
        int p = base + tid;
        bool ok = (p < n);
        ((int*)(dsm + OFF_TOK))[tid] = ok ? g_tok[e * NB + p] : 0;
        ((float*)(dsm + OFF_WT))[tid] = ok ? g_tw[e * NB + p] : 0.f;
    }
    __syncthreads();
    uint32_t sb = (uint32_t)__cvta_generic_to_shared(dsm);
    run_tile(dsm, sb, x, 1,
             w1f + (size_t)e * ND * NF,
             b1all + (size_t)e * NF,
             w2f + (size_t)e * NF * NO, out);
}

// ---------------- launch ----------------------------------------------------
extern "C" void kernel_launch(void* const* d_in, const int* in_sizes, int n_in,
                              void* d_out, int out_size)
{
    const float* x      = (const float*)d_in[0];
    const float* gate_w = (const float*)d_in[1];
    const float* gate_b = (const float*)d_in[2];
    const float* sh_w1  = (const float*)d_in[3];
    const float* sh_b1  = (const float*)d_in[4];
    const float* sh_w2  = (const float*)d_in[5];
    const float* sh_b2  = (const float*)d_in[6];
    const float* sp_w1  = (const float*)d_in[7];
    const float* sp_b1  = (const float*)d_in[8];
    const float* sp_w2  = (const float*)d_in[9];
    const float* sp_b2  = (const float*)d_in[10];

    float* out  = (float*)d_out;
    float* wout = out + (size_t)NB * NO;

    cudaFuncSetAttribute(shared_kernel, cudaFuncAttributeMaxDynamicSharedMemorySize, DSM_BYTES);
    cudaFuncSetAttribute(specific_kernel, cudaFuncAttributeMaxDynamicSharedMemorySize, DSM_BYTES);

    zero_cnt_kernel<<<1, 32>>>();
    gate_kernel<<<NB / 8, 256>>>(x, gate_w, gate_b, sh_b2, sp_b2, wout, out);
    shared_kernel<<<NB / MT, NT, DSM_BYTES>>>(x, sh_w1, sh_b1, sh_w2, out);
    specific_kernel<<<dim3(NB / MT, NES), NT, DSM_BYTES>>>(x, sp_w1, sp_b1, sp_w2, out);
}

// round 10
// speedup vs baseline: 2.6490x; 1.0327x over previous
#include <cuda_runtime.h>
#include <cuda_bf16.h>
#include <math.h>
#include <stdint.h>

#define NB 16384
#define ND 256
#define NF 1024
#define NO 256
#define NE 8
#define NS 2
#define NES 6
#define MT 128
#define NT 512

// smem row strides in bytes (16B pad keeps ldmatrix conflict-free)
#define XSB  528
#define HSB  144
#define W1SB 144
#define W2SB 528

// W chunk buffer sizes
#define W1CH (32 * W1SB)
#define W2CH (16 * W2SB)

// dynamic smem layout (bytes) — total 225536, 1 CTA/SM
#define OFF_TOK 0
#define OFF_WT  512
#define OFF_B1  1024
#define OFF_XH  1280
#define OFF_XL  (OFF_XH + MT * XSB)
#define OFF_HH  (OFF_XL + MT * XSB)
#define OFF_HL  (OFF_HH + MT * HSB)
#define OFF_W1  (OFF_HL + MT * HSB)
#define OFF_W2  (OFF_W1 + 4 * W1CH)
#define DSM_BYTES (OFF_W2 + 4 * W2CH)

// ---------------- device scratch -------------------------------------------
__device__ int   g_cnt[NES];
__device__ int   g_tok[NES * NB];
__device__ float g_tw [NES * NB];

// ---------------- PTX helpers ----------------------------------------------
__device__ __forceinline__ void ldsm_x4(uint32_t* a, uint32_t addr) {
    asm volatile("ldmatrix.sync.aligned.m8n8.x4.shared.b16 {%0,%1,%2,%3}, [%4];"
                 : "=r"(a[0]), "=r"(a[1]), "=r"(a[2]), "=r"(a[3]) : "r"(addr));
}
__device__ __forceinline__ void ldsm_x4t(uint32_t* b, uint32_t addr) {
    asm volatile("ldmatrix.sync.aligned.m8n8.x4.trans.shared.b16 {%0,%1,%2,%3}, [%4];"
                 : "=r"(b[0]), "=r"(b[1]), "=r"(b[2]), "=r"(b[3]) : "r"(addr));
}
__device__ __forceinline__ void mma16816(float* c, const uint32_t* a,
                                         uint32_t b0, uint32_t b1) {
    asm volatile(
        "mma.sync.aligned.m16n8k16.row.col.f32.bf16.bf16.f32 "
        "{%0,%1,%2,%3}, {%4,%5,%6,%7}, {%8,%9}, {%0,%1,%2,%3};"
        : "+f"(c[0]), "+f"(c[1]), "+f"(c[2]), "+f"(c[3])
        : "r"(a[0]), "r"(a[1]), "r"(a[2]), "r"(a[3]), "r"(b0), "r"(b1));
}
__device__ __forceinline__ void split2(float a, float b, uint32_t& hi, uint32_t& lo) {
    __nv_bfloat16 ha = __float2bfloat16_rn(a);
    __nv_bfloat16 hb = __float2bfloat16_rn(b);
    __nv_bfloat16 la = __float2bfloat16_rn(a - __bfloat162float(ha));
    __nv_bfloat16 lb = __float2bfloat16_rn(b - __bfloat162float(hb));
    hi = (uint32_t)__bfloat16_as_ushort(ha) | ((uint32_t)__bfloat16_as_ushort(hb) << 16);
    lo = (uint32_t)__bfloat16_as_ushort(la) | ((uint32_t)__bfloat16_as_ushort(lb) << 16);
}
__device__ __forceinline__ void split4(float4 v, uint2& hi, uint2& lo) {
    uint32_t h0, l0, h1, l1;
    split2(v.x, v.y, h0, l0);
    split2(v.z, v.w, h1, l1);
    hi = make_uint2(h0, h1);
    lo = make_uint2(l0, l1);
}

// ---------------- small kernels --------------------------------------------
__global__ void zero_cnt_kernel() {
    if (threadIdx.x < NES) g_cnt[threadIdx.x] = 0;
}

// ---------------- gating + output init -------------------------------------
__global__ __launch_bounds__(256) void gate_kernel(
    const float* __restrict__ x,
    const float* __restrict__ gw, const float* __restrict__ gb,
    const float* __restrict__ shb2, const float* __restrict__ spb2,
    float* __restrict__ wout, float* __restrict__ out)
{
    __shared__ float sgw[ND * NE];
    __shared__ float sgb[NE];
    __shared__ float sbsh[NO];
    __shared__ float sbsp[NES][NO];
    int tid = threadIdx.x;
    for (int i = tid; i < ND * NE; i += 256) sgw[i] = gw[i];
    if (tid < NE) sgb[tid] = gb[tid];
    for (int i = tid; i < NO; i += 256) sbsh[i] = 0.5f * (shb2[i] + shb2[NO + i]);
    for (int q = tid; q < NES * NO; q += 256) sbsp[q / NO][q % NO] = spb2[q];
    __syncthreads();

    int warp = tid >> 5, lane = tid & 31;
    int t = blockIdx.x * 8 + warp;
    const float* xr = x + (size_t)t * ND;
    float acc[NE];
    #pragma unroll
    for (int e = 0; e < NE; e++) acc[e] = 0.f;
    #pragma unroll
    for (int r = 0; r < ND / 32; r++) {
        int d = r * 32 + lane;
        float xv = xr[d];
        const float* g = &sgw[d * NE];
        #pragma unroll
        for (int e = 0; e < NE; e++) acc[e] += xv * g[e];
    }
    #pragma unroll
    for (int e = 0; e < NE; e++) {
        float v = acc[e];
        #pragma unroll
        for (int off = 16; off > 0; off >>= 1) v += __shfl_xor_sync(0xFFFFFFFFu, v, off);
        acc[e] = v + sgb[e];
    }
    float m = acc[0];
    #pragma unroll
    for (int e = 1; e < NE; e++) m = fmaxf(m, acc[e]);
    float s = 0.f, w[NE];
    #pragma unroll
    for (int e = 0; e < NE; e++) { w[e] = expf(acc[e] - m); s += w[e]; }
    float inv = 1.f / s;
    #pragma unroll
    for (int e = 0; e < NE; e++) w[e] *= inv;

    if (lane < NE) wout[(size_t)t * NE + lane] = w[lane];

    int i1 = 0, i2 = -1; float v1 = 0.f, v2 = 0.f;
    if (lane == 0) {
        v1 = w[0];
        #pragma unroll
        for (int e = 1; e < NE; e++) if (w[e] > v1) { v1 = w[e]; i1 = e; }
        v2 = -1.f;
        #pragma unroll
        for (int e = 0; e < NE; e++) if (e != i1 && w[e] > v2) { v2 = w[e]; i2 = e; }
        if (i1 >= NS) {
            int ex = i1 - NS;
            int p = atomicAdd(&g_cnt[ex], 1);
            g_tok[ex * NB + p] = t; g_tw[ex * NB + p] = v1;
        }
        if (i2 >= NS) {
            int ex = i2 - NS;
            int p = atomicAdd(&g_cnt[ex], 1);
            g_tok[ex * NB + p] = t; g_tw[ex * NB + p] = v2;
        }
    }
    i1 = __shfl_sync(0xFFFFFFFFu, i1, 0);
    i2 = __shfl_sync(0xFFFFFFFFu, i2, 0);
    v1 = __shfl_sync(0xFFFFFFFFu, v1, 0);
    v2 = __shfl_sync(0xFFFFFFFFu, v2, 0);

    for (int c = lane; c < NO; c += 32) {
        float val = sbsh[c];
        if (i1 >= NS) val += v1 * sbsp[i1 - NS][c];
        if (i2 >= NS) val += v2 * sbsp[i2 - NS][c];
        out[(size_t)t * NO + c] = val;
    }
}

// ---------------- fused expert tile: 128 tokens x 256 out, 512 threads -----
// Ping-pong W buffers: phase = { sync; STS(c+1); LDG(c+2); MMA(c) }.
__device__ __forceinline__ void run_tile(char* dsm, uint32_t sb,
                                         const float* __restrict__ x,
                                         int ge_cnt,
                                         const float* __restrict__ w1f,
                                         const float* __restrict__ b1all,
                                         const float* __restrict__ w2f,
                                         float* __restrict__ out)
{
    int tid = threadIdx.x;
    int wid = tid >> 5, lane = tid & 31;
    int lo16 = lane & 15, hi16 = lane >> 4;
    int* toks = (int*)(dsm + OFF_TOK);
    float* tws = (float*)(dsm + OFF_WT);
    float* b1s = (float*)(dsm + OFF_B1);

    // ---- x tile resident: 128 rows x 256 fp32 -> hi/lo bf16 (once) ----
    #pragma unroll
    for (int i = 0; i < 16; i++) {
        int q = i * NT + tid;
        int r = q >> 6, c = q & 63;
        float4 v = *(const float4*)(x + (size_t)toks[r] * ND + c * 4);
        uint2 hi, lo;
        split4(v, hi, lo);
        *(uint2*)(dsm + OFF_XH + r * XSB + c * 8) = hi;
        *(uint2*)(dsm + OFF_XL + r * XSB + c * 8) = lo;
    }

    int wm1 = wid & 7, wn1 = wid >> 3;   // GEMM1: 8x2 warps, 16x32 tiles
    int wm2 = wid & 3, wn2 = wid >> 2;   // GEMM2: 4x4 warps, 32x64 tiles

    int w1r = tid >> 4, w1c = tid & 15;
    int w2r0 = tid >> 6,        w2c0 = tid & 63;
    int w2r1 = (tid + NT) >> 6, w2c1 = (tid + NT) & 63;

    float c2[2][8][4];
    #pragma unroll
    for (int mi = 0; mi < 2; mi++)
        #pragma unroll
        for (int ni = 0; ni < 8; ni++)
            #pragma unroll
            for (int r = 0; r < 4; r++) c2[mi][ni][r] = 0.f;

    #pragma unroll 1
    for (int ei = 0; ei < ge_cnt; ei++) {
        const float* w1 = w1f + (size_t)ei * ND * NF;
        const float* w2 = w2f + (size_t)ei * NF * NO;
        const float* b1 = b1all + (size_t)ei * NF;

        #pragma unroll 1
        for (int fc = 0; fc < 16; fc++) {
            if (tid < 64) b1s[tid] = b1[fc * 64 + tid];
            float c1[4][4];
            #pragma unroll
            for (int ni = 0; ni < 4; ni++)
                #pragma unroll
                for (int r = 0; r < 4; r++) c1[ni][r] = 0.f;

            // ================= GEMM1: 8 chunks of 32 K-rows ================
            float4 pf = *(const float4*)(w1 + (size_t)w1r * NF + fc * 64 + w1c * 4);
            {
                uint2 hi, lo;
                split4(pf, hi, lo);
                *(uint2*)(dsm + OFF_W1 + w1r * W1SB + w1c * 8) = hi;
                *(uint2*)(dsm + OFF_W1 + W1CH + w1r * W1SB + w1c * 8) = lo;
                pf = *(const float4*)(w1 + (size_t)(32 + w1r) * NF + fc * 64 + w1c * 4);
            }
            #pragma unroll
            for (int c = 0; c < 8; c++) {
                __syncthreads();
                if (c < 7) {
                    uint32_t bo = OFF_W1 + ((c + 1) & 1) * (2 * W1CH);
                    uint2 hi, lo;
                    split4(pf, hi, lo);
                    *(uint2*)(dsm + bo + w1r * W1SB + w1c * 8) = hi;
                    *(uint2*)(dsm + bo + W1CH + w1r * W1SB + w1c * 8) = lo;
                }
                if (c < 6)
                    pf = *(const float4*)(w1 + (size_t)((c + 2) * 32 + w1r) * NF + fc * 64 + w1c * 4);
                uint32_t bH = OFF_W1 + (c & 1) * (2 * W1CH);
                uint32_t bL = bH + W1CH;
                #pragma unroll
                for (int ks2 = 0; ks2 < 2; ks2++) {
                    int kk = c * 32 + ks2 * 16;
                    uint32_t ah[4], al[4];
                    uint32_t arow = (uint32_t)((wm1 * 16 + lo16) * XSB + (kk + hi16 * 8) * 2);
                    ldsm_x4(ah, sb + OFF_XH + arow);
                    ldsm_x4(al, sb + OFF_XL + arow);
                    #pragma unroll
                    for (int np = 0; np < 2; np++) {
                        int n0 = wn1 * 32 + np * 16;
                        uint32_t brow = (uint32_t)((ks2 * 16 + lo16) * W1SB + (n0 + hi16 * 8) * 2);
                        uint32_t bh[4], bl[4];
                        ldsm_x4t(bh, sb + bH + brow);
                        ldsm_x4t(bl, sb + bL + brow);
                        mma16816(c1[np * 2],     ah, bh[0], bh[1]);
                        mma16816(c1[np * 2],     ah, bl[0], bl[1]);
                        mma16816(c1[np * 2],     al, bh[0], bh[1]);
                        mma16816(c1[np * 2 + 1], ah, bh[2], bh[3]);
                        mma16816(c1[np * 2 + 1], ah, bl[2], bl[3]);
                        mma16816(c1[np * 2 + 1], al, bh[2], bh[3]);
                    }
                }
            }

            // ---- issue W2 chunk0 LDG early; epilogue hides its latency ----
            float4 pw0 = *(const float4*)(w2 + (size_t)(fc * 64 + w2r0) * NO + w2c0 * 4);
            float4 pw1 = *(const float4*)(w2 + (size_t)(fc * 64 + w2r1) * NO + w2c1 * 4);

            // ---- epilogue: h = split(relu(c1 + b1)) -> H smem ----
            #pragma unroll
            for (int ni = 0; ni < 4; ni++) {
                int row = wm1 * 16 + (lane >> 2);
                int col = wn1 * 32 + ni * 8 + (lane & 3) * 2;
                float b0 = b1s[col], b1v = b1s[col + 1];
                float v00 = fmaxf(c1[ni][0] + b0, 0.f);
                float v01 = fmaxf(c1[ni][1] + b1v, 0.f);
                float v10 = fmaxf(c1[ni][2] + b0, 0.f);
                float v11 = fmaxf(c1[ni][3] + b1v, 0.f);
                uint32_t h0, l0, h1, l1;
                split2(v00, v01, h0, l0);
                split2(v10, v11, h1, l1);
                *(uint32_t*)(dsm + OFF_HH + row * HSB + col * 2) = h0;
                *(uint32_t*)(dsm + OFF_HL + row * HSB + col * 2) = l0;
                *(uint32_t*)(dsm + OFF_HH + (row + 8) * HSB + col * 2) = h1;
                *(uint32_t*)(dsm + OFF_HL + (row + 8) * HSB + col * 2) = l1;
            }

            // ================= GEMM2: 4 chunks of 16 K-rows ================
            {
                uint2 hi, lo;
                split4(pw0, hi, lo);
                *(uint2*)(dsm + OFF_W2 + w2r0 * W2SB + w2c0 * 8) = hi;
                *(uint2*)(dsm + OFF_W2 + W2CH + w2r0 * W2SB + w2c0 * 8) = lo;
                split4(pw1, hi, lo);
                *(uint2*)(dsm + OFF_W2 + w2r1 * W2SB + w2c1 * 8) = hi;
                *(uint2*)(dsm + OFF_W2 + W2CH + w2r1 * W2SB + w2c1 * 8) = lo;
                pw0 = *(const float4*)(w2 + (size_t)(fc * 64 + 16 + w2r0) * NO + w2c0 * 4);
                pw1 = *(const float4*)(w2 + (size_t)(fc * 64 + 16 + w2r1) * NO + w2c1 * 4);
            }
            #pragma unroll
            for (int c = 0; c < 4; c++) {
                __syncthreads();
                if (c < 3) {
                    uint32_t bo = OFF_W2 + ((c + 1) & 1) * (2 * W2CH);
                    uint2 hi, lo;
                    split4(pw0, hi, lo);
                    *(uint2*)(dsm + bo + w2r0 * W2SB + w2c0 * 8) = hi;
                    *(uint2*)(dsm + bo + W2CH + w2r0 * W2SB + w2c0 * 8) = lo;
                    split4(pw1, hi, lo);
                    *(uint2*)(dsm + bo + w2r1 * W2SB + w2c1 * 8) = hi;
                    *(uint2*)(dsm + bo + W2CH + w2r1 * W2SB + w2c1 * 8) = lo;
                }
                if (c < 2) {
                    pw0 = *(const float4*)(w2 + (size_t)(fc * 64 + (c + 2) * 16 + w2r0) * NO + w2c0 * 4);
                    pw1 = *(const float4*)(w2 + (size_t)(fc * 64 + (c + 2) * 16 + w2r1) * NO + w2c1 * 4);
                }
                uint32_t bH = OFF_W2 + (c & 1) * (2 * W2CH);
                uint32_t bL = bH + W2CH;
                uint32_t ah[2][4], al[2][4];
                #pragma unroll
                for (int mi = 0; mi < 2; mi++) {
                    uint32_t arow = (uint32_t)((wm2 * 32 + mi * 16 + lo16) * HSB
                                               + (c * 16 + hi16 * 8) * 2);
                    ldsm_x4(ah[mi], sb + OFF_HH + arow);
                    ldsm_x4(al[mi], sb + OFF_HL + arow);
                }
                #pragma unroll
                for (int np = 0; np < 4; np++) {
                    int n0 = wn2 * 64 + np * 16;
                    uint32_t brow = (uint32_t)(lo16 * W2SB + (n0 + hi16 * 8) * 2);
                    uint32_t bh[4], bl[4];
                    ldsm_x4t(bh, sb + bH + brow);
                    ldsm_x4t(bl, sb + bL + brow);
                    #pragma unroll
                    for (int mi = 0; mi < 2; mi++) {
                        mma16816(c2[mi][np * 2],     ah[mi], bh[0], bh[1]);
                        mma16816(c2[mi][np * 2],     ah[mi], bl[0], bl[1]);
                        mma16816(c2[mi][np * 2],     al[mi], bh[0], bh[1]);
                        mma16816(c2[mi][np * 2 + 1], ah[mi], bh[2], bh[3]);
                        mma16816(c2[mi][np * 2 + 1], ah[mi], bl[2], bl[3]);
                        mma16816(c2[mi][np * 2 + 1], al[mi], bh[2], bh[3]);
                    }
                }
            }
        }
    }

    // ---- final: weighted atomic accumulate ----
    #pragma unroll
    for (int mi = 0; mi < 2; mi++)
        #pragma unroll
        for (int ni = 0; ni < 8; ni++) {
            int row = wm2 * 32 + mi * 16 + (lane >> 2);
            int col = wn2 * 64 + ni * 8 + (lane & 3) * 2;
            int t0 = toks[row];     float w0 = tws[row];
            int t1 = toks[row + 8]; float w1 = tws[row + 8];
            atomicAdd(out + (size_t)t0 * NO + col,     w0 * c2[mi][ni][0]);
            atomicAdd(out + (size_t)t0 * NO + col + 1, w0 * c2[mi][ni][1]);
            atomicAdd(out + (size_t)t1 * NO + col,     w1 * c2[mi][ni][2]);
            atomicAdd(out + (size_t)t1 * NO + col + 1, w1 * c2[mi][ni][3]);
        }
}

// ---------------- unified expert kernel -------------------------------------
// grid = (NB/MT, 1 + NES). y=0: fused shared experts (heavy CTAs, launched
// first => good greedy schedule). y>=1: routed expert y-1 with early exit.
__global__ __launch_bounds__(NT, 1)
void moe_kernel(const float* __restrict__ x,
                const float* __restrict__ sh_w1, const float* __restrict__ sh_b1,
                const float* __restrict__ sh_w2,
                const float* __restrict__ sp_w1, const float* __restrict__ sp_b1,
                const float* __restrict__ sp_w2,
                float* __restrict__ out)
{
    extern __shared__ char dsm[];
    int tid = threadIdx.x;
    int ey = blockIdx.y;

    if (ey == 0) {
        int t0 = blockIdx.x * MT;
        if (tid < MT) {
            ((int*)(dsm + OFF_TOK))[tid] = t0 + tid;
            ((float*)(dsm + OFF_WT))[tid] = 0.5f;
        }
        __syncthreads();
        uint32_t sb = (uint32_t)__cvta_generic_to_shared(dsm);
        run_tile(dsm, sb, x, NS, sh_w1, sh_b1, sh_w2, out);
    } else {
        int e = ey - 1;
        int n = g_cnt[e];
        int base = blockIdx.x * MT;
        if (base >= n) return;
        if (tid < MT) {
            int p = base + tid;
            bool ok = (p < n);
            ((int*)(dsm + OFF_TOK))[tid] = ok ? g_tok[e * NB + p] : 0;
            ((float*)(dsm + OFF_WT))[tid] = ok ? g_tw[e * NB + p] : 0.f;
        }
        __syncthreads();
        uint32_t sb = (uint32_t)__cvta_generic_to_shared(dsm);
        run_tile(dsm, sb, x, 1,
                 sp_w1 + (size_t)e * ND * NF,
                 sp_b1 + (size_t)e * NF,
                 sp_w2 + (size_t)e * NF * NO, out);
    }
}

// ---------------- launch ----------------------------------------------------
extern "C" void kernel_launch(void* const* d_in, const int* in_sizes, int n_in,
                              void* d_out, int out_size)
{
    const float* x      = (const float*)d_in[0];
    const float* gate_w = (const float*)d_in[1];
    const float* gate_b = (const float*)d_in[2];
    const float* sh_w1  = (const float*)d_in[3];
    const float* sh_b1  = (const float*)d_in[4];
    const float* sh_w2  = (const float*)d_in[5];
    const float* sh_b2  = (const float*)d_in[6];
    const float* sp_w1  = (const float*)d_in[7];
    const float* sp_b1  = (const float*)d_in[8];
    const float* sp_w2  = (const float*)d_in[9];
    const float* sp_b2  = (const float*)d_in[10];

    float* out  = (float*)d_out;
    float* wout = out + (size_t)NB * NO;

    cudaFuncSetAttribute(moe_kernel, cudaFuncAttributeMaxDynamicSharedMemorySize, DSM_BYTES);

    zero_cnt_kernel<<<1, 32>>>();
    gate_kernel<<<NB / 8, 256>>>(x, gate_w, gate_b, sh_b2, sp_b2, wout, out);
    moe_kernel<<<dim3(NB / MT, 1 + NES), NT, DSM_BYTES>>>(
        x, sh_w1, sh_b1, sh_w2, sp_w1, sp_b1, sp_w2, out);
}